// round 2
// baseline (speedup 1.0000x reference)
#include <cuda_runtime.h>
#include <cuda_bf16.h>
#include <cstdint>

// ============================================================================
// PuzzleSim: out[p] = max over (n,q) of <img_n[:,p], refs_n[n,:,q]>
// GEMM D[2304 x 73728] (K=128) + row-max.
// Tensor path: mma.sync.m16n8k16 bf16 (sm_100 base target: no tcgen05!)
// Precision: bf16x3 split (hi*hi + hi*lo + lo*hi), fp32 accumulate.
// ============================================================================

#define NREF    32
#define CCH     128
#define HW      2304            // 48*48
#define JTOT    (NREF * HW)     // 73728
#define CP      64              // u32 (bf16 pairs) per row
#define MT      128
#define NT      128
#define MTILES  (HW / MT)       // 18
#define NBLK    (JTOT / NT)     // 576
#define TILE_BYTES 32768        // 128 rows x 256 B (128 bf16)
#define DSMEM_BYTES (4 * TILE_BYTES)

// ---- device scratch (allocation-free rule: __device__ globals) ----
__device__ uint32_t g_refsHi[(size_t)JTOT * CP];
__device__ uint32_t g_refsLo[(size_t)JTOT * CP];
__device__ uint32_t g_imgHi[(size_t)HW * CP];
__device__ uint32_t g_imgLo[(size_t)HW * CP];
__device__ unsigned g_pmax[HW];

// ============================================================================
// helpers
// ============================================================================
__device__ __forceinline__ uint32_t smem_u32(const void* p) {
    uint32_t a;
    asm("{ .reg .u64 t; cvta.to.shared.u64 t, %1; cvt.u32.u64 %0, t; }"
        : "=r"(a) : "l"(p));
    return a;
}
__device__ __forceinline__ void ldsm4(uint32_t& r0, uint32_t& r1, uint32_t& r2,
                                      uint32_t& r3, uint32_t addr) {
    asm volatile("ldmatrix.sync.aligned.m8n8.x4.shared.b16 {%0,%1,%2,%3}, [%4];"
                 : "=r"(r0), "=r"(r1), "=r"(r2), "=r"(r3) : "r"(addr));
}
__device__ __forceinline__ void mma16816(float* c, const uint32_t* a,
                                         const uint32_t* b) {
    asm volatile(
        "mma.sync.aligned.m16n8k16.row.col.f32.bf16.bf16.f32 "
        "{%0,%1,%2,%3}, {%4,%5,%6,%7}, {%8,%9}, {%0,%1,%2,%3};"
        : "+f"(c[0]), "+f"(c[1]), "+f"(c[2]), "+f"(c[3])
        : "r"(a[0]), "r"(a[1]), "r"(a[2]), "r"(a[3]), "r"(b[0]), "r"(b[1]));
}

// monotone float<->uint mapping for atomicMax on signed floats
__device__ __forceinline__ unsigned fkey(float f) {
    unsigned u = __float_as_uint(f);
    return (u & 0x80000000u) ? ~u : (u | 0x80000000u);
}
__device__ __forceinline__ float finv(unsigned k) {
    unsigned u = (k & 0x80000000u) ? (k & 0x7fffffffu) : ~k;
    return __uint_as_float(u);
}
__device__ __forceinline__ uint32_t pack2(__nv_bfloat16 a, __nv_bfloat16 b) {
    return (uint32_t)__bfloat16_as_ushort(a) | ((uint32_t)__bfloat16_as_ushort(b) << 16);
}

// ============================================================================
// K0: init partial-max keys (0 < fkey(-inf), safe lower bound; always updated)
// ============================================================================
__global__ void k_init() {
    int p = blockIdx.x * blockDim.x + threadIdx.x;
    if (p < HW) g_pmax[p] = 0u;
}

// ============================================================================
// K1: normalize img over C per position, split into packed bf16 hi/lo pairs
// img layout: (C, HW) c-major
// ============================================================================
__global__ void k_prep_img(const float* __restrict__ img) {
    int p = blockIdx.x * blockDim.x + threadIdx.x;
    if (p >= HW) return;
    float ss = 0.f;
    #pragma unroll 8
    for (int c = 0; c < CCH; c++) { float v = img[c * HW + p]; ss += v * v; }
    float scale = 1.0f / fmaxf(sqrtf(ss), 1e-12f);
    #pragma unroll 4
    for (int k = 0; k < CP; k++) {
        float v0 = img[(2 * k) * HW + p] * scale;
        float v1 = img[(2 * k + 1) * HW + p] * scale;
        __nv_bfloat16 h0 = __float2bfloat16(v0), h1 = __float2bfloat16(v1);
        __nv_bfloat16 l0 = __float2bfloat16(v0 - __bfloat162float(h0));
        __nv_bfloat16 l1 = __float2bfloat16(v1 - __bfloat162float(h1));
        g_imgHi[(size_t)p * CP + k] = pack2(h0, h1);
        g_imgLo[(size_t)p * CP + k] = pack2(l0, l1);
    }
}

// ============================================================================
// K2: normalize refs over C per (n,q), split hi/lo, write [j][64 u32] row-major
// via SMEM staging so both reads and writes stay coalesced.
// refs layout: (N, C, HW). Block = 256 consecutive j within one n (2304=9*256).
// ============================================================================
__global__ __launch_bounds__(256) void k_prep_refs(const float* __restrict__ refs) {
    __shared__ uint32_t sthi[256 * 9];
    __shared__ uint32_t stlo[256 * 9];
    const int tid = threadIdx.x;
    const int j0 = blockIdx.x * 256;
    const int j = j0 + tid;
    const int n = j / HW, q = j - n * HW;
    const float* base = refs + (size_t)n * (CCH * HW) + q;

    float ss = 0.f;
    #pragma unroll 8
    for (int c = 0; c < CCH; c++) { float v = base[(size_t)c * HW]; ss += v * v; }
    float scale = 1.0f / fmaxf(sqrtf(ss), 1e-12f);

    for (int chunk = 0; chunk < 8; chunk++) {        // 16 channels per chunk
        #pragma unroll
        for (int k = 0; k < 8; k++) {
            int c = chunk * 16 + 2 * k;
            float v0 = base[(size_t)c * HW] * scale;
            float v1 = base[(size_t)(c + 1) * HW] * scale;
            __nv_bfloat16 h0 = __float2bfloat16(v0), h1 = __float2bfloat16(v1);
            __nv_bfloat16 l0 = __float2bfloat16(v0 - __bfloat162float(h0));
            __nv_bfloat16 l1 = __float2bfloat16(v1 - __bfloat162float(h1));
            sthi[tid * 9 + k] = pack2(h0, h1);
            stlo[tid * 9 + k] = pack2(l0, l1);
        }
        __syncthreads();
        #pragma unroll
        for (int i = 0; i < 8; i++) {                // 2048 u32 per array
            int lin = i * 256 + tid;
            int row = lin >> 3, k = lin & 7;
            size_t dst = (size_t)(j0 + row) * CP + chunk * 8 + k;
            g_refsHi[dst] = sthi[row * 9 + k];
            g_refsLo[dst] = stlo[row * 9 + k];
        }
        __syncthreads();
    }
}

// ============================================================================
// K3: main GEMM+max. One block per 128-wide refs (B/N) tile; loop over all 18
// img (A/M) tiles. 256 thr, 8 warps in 4(M)x2(N), warp tile 32x64.
// SMEM tile: row-major [128][256B] with 16B-chunk XOR swizzle c^=(row&7)
// -> conflict-free for uint4 fills AND ldmatrix.
// ============================================================================
__device__ __forceinline__ void fill_tile(char* dst, const uint32_t* __restrict__ src,
                                          int tid) {
    const uint4* s = (const uint4*)src;
    #pragma unroll
    for (int i = 0; i < 8; i++) {
        int lin = i * 256 + tid;               // 0..2047 uint4s
        int row = lin >> 4, c = lin & 15;
        *reinterpret_cast<uint4*>(dst + row * 256 + ((c ^ (row & 7)) << 4)) = s[lin];
    }
}

__global__ __launch_bounds__(256, 1) void k_gemm_max() {
    extern __shared__ char sm[];
    const int tid = threadIdx.x, wid = tid >> 5, lane = tid & 31;
    const int wm = wid >> 1, wn = wid & 1;
    const uint32_t sbase = smem_u32(sm);
    const uint32_t Bhi = sbase, Blo = sbase + TILE_BYTES;
    const uint32_t Ahi = sbase + 2 * TILE_BYTES, Alo = sbase + 3 * TILE_BYTES;

    const int j0 = blockIdx.x * NT;
    fill_tile(sm, g_refsHi + (size_t)j0 * CP, tid);
    fill_tile(sm + TILE_BYTES, g_refsLo + (size_t)j0 * CP, tid);

    // per-lane ldmatrix row precompute (lane&15 = matrix row, lane>>4 = k half)
    uint32_t aoff[2], asw[2], boff[4], bsw[4];
    #pragma unroll
    for (int mf = 0; mf < 2; mf++) {
        int r = wm * 32 + mf * 16 + (lane & 15);
        aoff[mf] = r * 256; asw[mf] = r & 7;
    }
    #pragma unroll
    for (int g = 0; g < 4; g++) {
        int r = wn * 64 + g * 16 + (lane & 15);
        boff[g] = r * 256; bsw[g] = r & 7;
    }
    const uint32_t chi = lane >> 4;

    for (int m = 0; m < MTILES; m++) {
        __syncthreads();                        // prev iter's ldsm done
        const int p0 = m * MT;
        fill_tile(sm + 2 * TILE_BYTES, g_imgHi + (size_t)p0 * CP, tid);
        fill_tile(sm + 3 * TILE_BYTES, g_imgLo + (size_t)p0 * CP, tid);
        __syncthreads();

        float acc[2][8][4];
        #pragma unroll
        for (int i = 0; i < 2; i++)
            #pragma unroll
            for (int j = 0; j < 8; j++)
                #pragma unroll
                for (int k = 0; k < 4; k++) acc[i][j][k] = 0.f;

        #pragma unroll 1
        for (int pass = 0; pass < 3; pass++) {  // hh, hl, lh
            uint32_t Ab = (pass == 2) ? Alo : Ahi;
            uint32_t Bb = (pass == 1) ? Blo : Bhi;
            #pragma unroll
            for (int ks = 0; ks < 8; ks++) {
                uint32_t c = (uint32_t)(ks * 2) + chi;
                uint32_t a[2][4], b[8][2];
                #pragma unroll
                for (int mf = 0; mf < 2; mf++)
                    ldsm4(a[mf][0], a[mf][1], a[mf][2], a[mf][3],
                          Ab + aoff[mf] + ((c ^ asw[mf]) << 4));
                #pragma unroll
                for (int g = 0; g < 4; g++) {
                    uint32_t t0, t1, t2, t3;
                    ldsm4(t0, t1, t2, t3, Bb + boff[g] + ((c ^ bsw[g]) << 4));
                    b[2 * g][0] = t0; b[2 * g][1] = t2;
                    b[2 * g + 1][0] = t1; b[2 * g + 1][1] = t3;
                }
                #pragma unroll
                for (int mf = 0; mf < 2; mf++)
                    #pragma unroll
                    for (int nf = 0; nf < 8; nf++)
                        mma16816(acc[mf][nf], a[mf], b[nf]);
            }
        }

        // Epilogue: row max. C frag: lane row = lane/4 (+8), cols 2*(lane&3)+{0,1}
        #pragma unroll
        for (int mf = 0; mf < 2; mf++) {
            float m0 = fmaxf(acc[mf][0][0], acc[mf][0][1]);
            float m1 = fmaxf(acc[mf][0][2], acc[mf][0][3]);
            #pragma unroll
            for (int nf = 1; nf < 8; nf++) {
                m0 = fmaxf(m0, fmaxf(acc[mf][nf][0], acc[mf][nf][1]));
                m1 = fmaxf(m1, fmaxf(acc[mf][nf][2], acc[mf][nf][3]));
            }
            m0 = fmaxf(m0, __shfl_xor_sync(0xffffffffu, m0, 1));
            m0 = fmaxf(m0, __shfl_xor_sync(0xffffffffu, m0, 2));
            m1 = fmaxf(m1, __shfl_xor_sync(0xffffffffu, m1, 1));
            m1 = fmaxf(m1, __shfl_xor_sync(0xffffffffu, m1, 2));
            if ((lane & 3) == 0) {
                int row = p0 + wm * 32 + mf * 16 + (lane >> 2);
                atomicMax(&g_pmax[row], fkey(m0));
                atomicMax(&g_pmax[row + 8], fkey(m1));
            }
        }
    }
}

// ============================================================================
// K4: decode keys to floats into d_out
// ============================================================================
__global__ void k_final(float* __restrict__ out) {
    int p = blockIdx.x * blockDim.x + threadIdx.x;
    if (p < HW) out[p] = finv(g_pmax[p]);
}

// ============================================================================
extern "C" void kernel_launch(void* const* d_in, const int* in_sizes, int n_in,
                              void* d_out, int out_size) {
    const float* refs = (const float*)d_in[0];
    const float* img  = (const float*)d_in[1];
    float* out = (float*)d_out;

    cudaFuncSetAttribute(k_gemm_max, cudaFuncAttributeMaxDynamicSharedMemorySize,
                         DSMEM_BYTES);

    k_init<<<(HW + 255) / 256, 256>>>();
    k_prep_img<<<(HW + 255) / 256, 256>>>(img);
    k_prep_refs<<<JTOT / 256, 256>>>(refs);
    k_gemm_max<<<NBLK, 256, DSMEM_BYTES>>>();
    k_final<<<(HW + 255) / 256, 256>>>(out);
}

// round 3
// speedup vs baseline: 1.1320x; 1.1320x over previous
#include <cuda_runtime.h>
#include <cuda_bf16.h>
#include <cstdint>

// ============================================================================
// PuzzleSim: out[p] = max over (n,q) of <img_n[:,p], refs_n[n,:,q]>
// GEMM D[2304 x 73728] (K=128) + row-max, mma.sync m16n8k16 bf16, bf16x3 split.
// R3: loop-swap (CTA = (img tile, ref n), stream refs) + cp.async double-buffer
// so the tensor pipe never waits on fills; epilogue hoisted out of the loop.
// ============================================================================

#define NREF    32
#define CCH     128
#define HW      2304            // 48*48
#define JTOT    (NREF * HW)     // 73728
#define CP      64              // u32 (bf16 pairs) per row
#define MT      128
#define NT      128
#define NTILES  (HW / NT)       // 18 B-tiles per ref image
#define MTILES  (HW / MT)       // 18
#define NBLK    (MTILES * NREF) // 576
#define TILE_BYTES 32768        // 128 rows x 256 B (128 bf16)
// smem: A hi+lo (64KB) + B double buffer (2 x 64KB) = 192KB
#define DSMEM_BYTES (6 * TILE_BYTES)

// ---- device scratch (allocation-free rule: __device__ globals) ----
__device__ uint32_t g_refsHi[(size_t)JTOT * CP];
__device__ uint32_t g_refsLo[(size_t)JTOT * CP];
__device__ uint32_t g_imgHi[(size_t)HW * CP];
__device__ uint32_t g_imgLo[(size_t)HW * CP];
__device__ unsigned g_pmax[HW];

// ============================================================================
// helpers
// ============================================================================
__device__ __forceinline__ uint32_t smem_u32(const void* p) {
    uint32_t a;
    asm("{ .reg .u64 t; cvta.to.shared.u64 t, %1; cvt.u32.u64 %0, t; }"
        : "=r"(a) : "l"(p));
    return a;
}
__device__ __forceinline__ void ldsm4(uint32_t& r0, uint32_t& r1, uint32_t& r2,
                                      uint32_t& r3, uint32_t addr) {
    asm volatile("ldmatrix.sync.aligned.m8n8.x4.shared.b16 {%0,%1,%2,%3}, [%4];"
                 : "=r"(r0), "=r"(r1), "=r"(r2), "=r"(r3) : "r"(addr));
}
__device__ __forceinline__ void mma16816(float* c, const uint32_t* a,
                                         const uint32_t* b) {
    asm volatile(
        "mma.sync.aligned.m16n8k16.row.col.f32.bf16.bf16.f32 "
        "{%0,%1,%2,%3}, {%4,%5,%6,%7}, {%8,%9}, {%0,%1,%2,%3};"
        : "+f"(c[0]), "+f"(c[1]), "+f"(c[2]), "+f"(c[3])
        : "r"(a[0]), "r"(a[1]), "r"(a[2]), "r"(a[3]), "r"(b[0]), "r"(b[1]));
}
#define CP_ASYNC16(dst, src) \
    asm volatile("cp.async.cg.shared.global [%0], [%1], 16;" \
                 :: "r"(dst), "l"(src) : "memory")
#define CP_COMMIT()  asm volatile("cp.async.commit_group;" ::: "memory")
#define CP_WAIT0()   asm volatile("cp.async.wait_group 0;" ::: "memory")

// monotone float<->uint mapping for atomicMax on signed floats
__device__ __forceinline__ unsigned fkey(float f) {
    unsigned u = __float_as_uint(f);
    return (u & 0x80000000u) ? ~u : (u | 0x80000000u);
}
__device__ __forceinline__ float finv(unsigned k) {
    unsigned u = (k & 0x80000000u) ? (k & 0x7fffffffu) : ~k;
    return __uint_as_float(u);
}
__device__ __forceinline__ uint32_t pack2(__nv_bfloat16 a, __nv_bfloat16 b) {
    return (uint32_t)__bfloat16_as_ushort(a) | ((uint32_t)__bfloat16_as_ushort(b) << 16);
}

// ============================================================================
// K0: init partial-max keys (0 < fkey of any finite value we produce)
// ============================================================================
__global__ void k_init() {
    int p = blockIdx.x * blockDim.x + threadIdx.x;
    if (p < HW) g_pmax[p] = 0u;
}

// ============================================================================
// K1: normalize img over C per position, split into packed bf16 hi/lo pairs
// ============================================================================
__global__ void k_prep_img(const float* __restrict__ img) {
    int p = blockIdx.x * blockDim.x + threadIdx.x;
    if (p >= HW) return;
    float ss = 0.f;
    #pragma unroll 8
    for (int c = 0; c < CCH; c++) { float v = img[c * HW + p]; ss += v * v; }
    float scale = 1.0f / fmaxf(sqrtf(ss), 1e-12f);
    #pragma unroll 4
    for (int k = 0; k < CP; k++) {
        float v0 = img[(2 * k) * HW + p] * scale;
        float v1 = img[(2 * k + 1) * HW + p] * scale;
        __nv_bfloat16 h0 = __float2bfloat16(v0), h1 = __float2bfloat16(v1);
        __nv_bfloat16 l0 = __float2bfloat16(v0 - __bfloat162float(h0));
        __nv_bfloat16 l1 = __float2bfloat16(v1 - __bfloat162float(h1));
        g_imgHi[(size_t)p * CP + k] = pack2(h0, h1);
        g_imgLo[(size_t)p * CP + k] = pack2(l0, l1);
    }
}

// ============================================================================
// K2: normalize refs over C per (n,q), split hi/lo, write [j][64 u32] row-major
// via SMEM staging so both reads and writes stay coalesced.
// ============================================================================
__global__ __launch_bounds__(256) void k_prep_refs(const float* __restrict__ refs) {
    __shared__ uint32_t sthi[256 * 9];
    __shared__ uint32_t stlo[256 * 9];
    const int tid = threadIdx.x;
    const int j0 = blockIdx.x * 256;
    const int j = j0 + tid;
    const int n = j / HW, q = j - n * HW;
    const float* base = refs + (size_t)n * (CCH * HW) + q;

    float ss = 0.f;
    #pragma unroll 8
    for (int c = 0; c < CCH; c++) { float v = base[(size_t)c * HW]; ss += v * v; }
    float scale = 1.0f / fmaxf(sqrtf(ss), 1e-12f);

    for (int chunk = 0; chunk < 8; chunk++) {        // 16 channels per chunk
        #pragma unroll
        for (int k = 0; k < 8; k++) {
            int c = chunk * 16 + 2 * k;
            float v0 = base[(size_t)c * HW] * scale;
            float v1 = base[(size_t)(c + 1) * HW] * scale;
            __nv_bfloat16 h0 = __float2bfloat16(v0), h1 = __float2bfloat16(v1);
            __nv_bfloat16 l0 = __float2bfloat16(v0 - __bfloat162float(h0));
            __nv_bfloat16 l1 = __float2bfloat16(v1 - __bfloat162float(h1));
            sthi[tid * 9 + k] = pack2(h0, h1);
            stlo[tid * 9 + k] = pack2(l0, l1);
        }
        __syncthreads();
        #pragma unroll
        for (int i = 0; i < 8; i++) {                // 2048 u32 per array
            int lin = i * 256 + tid;
            int row = lin >> 3, k = lin & 7;
            size_t dst = (size_t)(j0 + row) * CP + chunk * 8 + k;
            g_refsHi[dst] = sthi[row * 9 + k];
            g_refsLo[dst] = stlo[row * 9 + k];
        }
        __syncthreads();
    }
}

// ============================================================================
// K3: main GEMM+max. CTA = (img m-tile bm, ref image bn). A (img hi+lo) loaded
// once; stream 18 refs B-tiles with cp.async double buffering. Row max kept in
// registers across the loop; one shfl-reduce + atomic set at the end.
// SMEM tile: row-major [128][256B], 16B-chunk XOR swizzle c^=(row&7) ->
// conflict-free for both cp.async 16B fills and ldmatrix.
// ============================================================================
__device__ __forceinline__ void fill_tile_async(uint32_t dst,
                                                const uint32_t* __restrict__ src,
                                                int tid) {
    const uint4* s = (const uint4*)src;
    #pragma unroll
    for (int i = 0; i < 8; i++) {
        int lin = i * 256 + tid;               // 0..2047 uint4s
        int row = lin >> 4, c = lin & 15;
        CP_ASYNC16(dst + row * 256 + ((c ^ (row & 7)) << 4), s + lin);
    }
}

__global__ __launch_bounds__(256, 1) void k_gemm_max() {
    extern __shared__ char sm[];
    const int tid = threadIdx.x, wid = tid >> 5, lane = tid & 31;
    const int wm = wid >> 1, wn = wid & 1;
    const uint32_t sbase = smem_u32(sm);
    const uint32_t Ahi = sbase, Alo = sbase + TILE_BYTES;
    const uint32_t Bbuf0 = sbase + 2 * TILE_BYTES;   // hi at +0, lo at +32KB
    const uint32_t Bbuf1 = sbase + 4 * TILE_BYTES;

    const int bm = blockIdx.x % MTILES;       // img tile
    const int bn = blockIdx.x / MTILES;       // ref image
    const int p0 = bm * MT;
    const uint32_t* refHi = g_refsHi + (size_t)bn * HW * CP;
    const uint32_t* refLo = g_refsLo + (size_t)bn * HW * CP;

    // prologue: A (once) + B tile 0 into buf0, one cp.async group
    fill_tile_async(Ahi, g_imgHi + (size_t)p0 * CP, tid);
    fill_tile_async(Alo, g_imgLo + (size_t)p0 * CP, tid);
    fill_tile_async(Bbuf0, refHi, tid);
    fill_tile_async(Bbuf0 + TILE_BYTES, refLo, tid);
    CP_COMMIT();

    // per-lane ldmatrix row precompute (lane&15 = matrix row)
    uint32_t aoff[2], asw[2], boff[4], bsw[4];
    #pragma unroll
    for (int mf = 0; mf < 2; mf++) {
        int r = wm * 32 + mf * 16 + (lane & 15);
        aoff[mf] = r * 256; asw[mf] = r & 7;
    }
    #pragma unroll
    for (int g = 0; g < 4; g++) {
        int r = wn * 64 + g * 16 + (lane & 15);
        boff[g] = r * 256; bsw[g] = r & 7;
    }
    const uint32_t chi = lane >> 4;

    float rm0[2], rm1[2];
    #pragma unroll
    for (int mf = 0; mf < 2; mf++) {
        rm0[mf] = __uint_as_float(0xff800000u);
        rm1[mf] = __uint_as_float(0xff800000u);
    }

    for (int t = 0; t < NTILES; t++) {
        CP_WAIT0();                            // tile t landed
        __syncthreads();                       // ...for all threads; prev reads done

        if (t + 1 < NTILES) {                  // prefetch t+1 into other buffer
            uint32_t nb = ((t + 1) & 1) ? Bbuf1 : Bbuf0;
            fill_tile_async(nb, refHi + (size_t)(t + 1) * NT * CP, tid);
            fill_tile_async(nb + TILE_BYTES, refLo + (size_t)(t + 1) * NT * CP, tid);
            CP_COMMIT();
        }

        const uint32_t Bb = (t & 1) ? Bbuf1 : Bbuf0;

        float acc[2][8][4];
        #pragma unroll
        for (int i = 0; i < 2; i++)
            #pragma unroll
            for (int j = 0; j < 8; j++)
                #pragma unroll
                for (int k = 0; k < 4; k++) acc[i][j][k] = 0.f;

        #pragma unroll 1
        for (int pass = 0; pass < 3; pass++) {  // hh, hl, lh
            uint32_t Ab = (pass == 2) ? Alo : Ahi;
            uint32_t Bp = (pass == 1) ? Bb + TILE_BYTES : Bb;
            #pragma unroll
            for (int ks = 0; ks < 8; ks++) {
                uint32_t c = (uint32_t)(ks * 2) + chi;
                uint32_t a[2][4], b[8][2];
                #pragma unroll
                for (int mf = 0; mf < 2; mf++)
                    ldsm4(a[mf][0], a[mf][1], a[mf][2], a[mf][3],
                          Ab + aoff[mf] + ((c ^ asw[mf]) << 4));
                #pragma unroll
                for (int g = 0; g < 4; g++) {
                    uint32_t t0, t1, t2, t3;
                    ldsm4(t0, t1, t2, t3, Bp + boff[g] + ((c ^ bsw[g]) << 4));
                    b[2 * g][0] = t0; b[2 * g][1] = t2;
                    b[2 * g + 1][0] = t1; b[2 * g + 1][1] = t3;
                }
                #pragma unroll
                for (int mf = 0; mf < 2; mf++)
                    #pragma unroll
                    for (int nf = 0; nf < 8; nf++)
                        mma16816(acc[mf][nf], a[mf], b[nf]);
            }
        }

        // fold this tile's 128 columns into the running row max (registers)
        #pragma unroll
        for (int mf = 0; mf < 2; mf++) {
            #pragma unroll
            for (int nf = 0; nf < 8; nf++) {
                rm0[mf] = fmaxf(rm0[mf], fmaxf(acc[mf][nf][0], acc[mf][nf][1]));
                rm1[mf] = fmaxf(rm1[mf], fmaxf(acc[mf][nf][2], acc[mf][nf][3]));
            }
        }
    }

    // final epilogue: reduce across the 4 lanes sharing a row, then atomics
    #pragma unroll
    for (int mf = 0; mf < 2; mf++) {
        float m0 = rm0[mf], m1 = rm1[mf];
        m0 = fmaxf(m0, __shfl_xor_sync(0xffffffffu, m0, 1));
        m0 = fmaxf(m0, __shfl_xor_sync(0xffffffffu, m0, 2));
        m1 = fmaxf(m1, __shfl_xor_sync(0xffffffffu, m1, 1));
        m1 = fmaxf(m1, __shfl_xor_sync(0xffffffffu, m1, 2));
        if ((lane & 3) == 0) {
            int row = p0 + wm * 32 + mf * 16 + (lane >> 2);
            atomicMax(&g_pmax[row], fkey(m0));
            atomicMax(&g_pmax[row + 8], fkey(m1));
        }
    }
}

// ============================================================================
// K4: decode keys to floats into d_out
// ============================================================================
__global__ void k_final(float* __restrict__ out) {
    int p = blockIdx.x * blockDim.x + threadIdx.x;
    if (p < HW) out[p] = finv(g_pmax[p]);
}

// ============================================================================
extern "C" void kernel_launch(void* const* d_in, const int* in_sizes, int n_in,
                              void* d_out, int out_size) {
    const float* refs = (const float*)d_in[0];
    const float* img  = (const float*)d_in[1];
    float* out = (float*)d_out;

    cudaFuncSetAttribute(k_gemm_max, cudaFuncAttributeMaxDynamicSharedMemorySize,
                         DSMEM_BYTES);

    k_init<<<(HW + 255) / 256, 256>>>();
    k_prep_img<<<(HW + 255) / 256, 256>>>(img);
    k_prep_refs<<<JTOT / 256, 256>>>(refs);
    k_gemm_max<<<NBLK, 256, DSMEM_BYTES>>>();
    k_final<<<(HW + 255) / 256, 256>>>(out);
}

// round 5
// speedup vs baseline: 1.7865x; 1.5781x over previous
#include <cuda_runtime.h>
#include <cuda_bf16.h>
#include <cstdint>

// ============================================================================
// PuzzleSim: out[p] = max over (n,q) of <img_n[:,p], refs_n[n,:,q]>
// GEMM D[2304 x 73728] (K=128) + row-max.
// R5 = R4 with the cvt.rna.tf32 output constraint fixed (.b32 reg, not f32).
// Single-pass tf32 mma.sync m16n8k8; fragment-linear operand layout so frag
// loads are 1x LDS.128 (A) / 1x LDS.64 (B); A resident, B double-buffered.
// ============================================================================

#define NREF    32
#define CCH     128
#define HW      2304            // 48*48
#define MT      128
#define NT      128
#define NTILES  (HW / NT)       // 18 B-tiles per ref image
#define MTILES  (HW / MT)       // 18
#define NBLK    (MTILES * NREF) // 576
#define TILE_FLOATS 16384       // 128 rows x 128 k fp32(tf32)
#define TILE_BYTES  65536
#define DSMEM_GEMM  (3 * TILE_BYTES)      // A + 2 B stages = 192KB
#define DSMEM_PREP  (128 * 129 * 4)       // 66048B staging

// ---- device scratch (allocation-free rule: __device__ globals) ----
// A-layout (img),  per m-tile:  [m16][k8][lane][4]  (a0,a1,a2,a3)
// B-layout (refs), per (bn,t):  [n8 ][k8][lane][2]  (b0,b1)
__device__ float g_imgT[(size_t)MTILES * TILE_FLOATS];
__device__ float g_refsT[(size_t)NREF * NTILES * TILE_FLOATS];
__device__ unsigned g_pmax[HW];

// ============================================================================
// helpers
// ============================================================================
__device__ __forceinline__ uint32_t smem_u32(const void* p) {
    uint32_t a;
    asm("{ .reg .u64 t; cvta.to.shared.u64 t, %1; cvt.u32.u64 %0, t; }"
        : "=r"(a) : "l"(p));
    return a;
}
// tf32 round: result lives in a .b32 register per PTX spec
__device__ __forceinline__ float tf32r(float x) {
    uint32_t y;
    asm("cvt.rna.tf32.f32 %0, %1;" : "=r"(y) : "f"(x));
    return __uint_as_float(y);
}
__device__ __forceinline__ void mma_tf32(float* c, const uint32_t* a,
                                         const uint32_t* b) {
    asm volatile(
        "mma.sync.aligned.m16n8k8.row.col.f32.tf32.tf32.f32 "
        "{%0,%1,%2,%3}, {%4,%5,%6,%7}, {%8,%9}, {%0,%1,%2,%3};"
        : "+f"(c[0]), "+f"(c[1]), "+f"(c[2]), "+f"(c[3])
        : "r"(a[0]), "r"(a[1]), "r"(a[2]), "r"(a[3]), "r"(b[0]), "r"(b[1]));
}
#define CP_ASYNC16(dst, src) \
    asm volatile("cp.async.cg.shared.global [%0], [%1], 16;" \
                 :: "r"(dst), "l"(src) : "memory")
#define CP_COMMIT()  asm volatile("cp.async.commit_group;" ::: "memory")
#define CP_WAIT0()   asm volatile("cp.async.wait_group 0;" ::: "memory")

// monotone float<->uint mapping for atomicMax on signed floats
__device__ __forceinline__ unsigned fkey(float f) {
    unsigned u = __float_as_uint(f);
    return (u & 0x80000000u) ? ~u : (u | 0x80000000u);
}
__device__ __forceinline__ float finv(unsigned k) {
    unsigned u = (k & 0x80000000u) ? (k & 0x7fffffffu) : ~k;
    return __uint_as_float(u);
}

// ============================================================================
// K0: init partial-max keys
// ============================================================================
__global__ void k_init() {
    int p = blockIdx.x * blockDim.x + threadIdx.x;
    if (p < HW) g_pmax[p] = 0u;
}

// ============================================================================
// K1: img -> normalized tf32, A-fragment-linear. 18 blocks x 128 thr.
// Stage s[128][129] (pad 129 -> conflict-free col writes).
// ============================================================================
__global__ __launch_bounds__(128) void k_prep_img(const float* __restrict__ img) {
    extern __shared__ float s[];                 // [128][129]
    const int tid = threadIdx.x;
    const int p = blockIdx.x * 128 + tid;

    float ss = 0.f;
    #pragma unroll 8
    for (int c = 0; c < CCH; c++) {
        float v = img[c * HW + p];
        s[tid * 129 + c] = v;
        ss += v * v;
    }
    float scale = 1.0f / fmaxf(sqrtf(ss), 1e-12f);
    #pragma unroll 8
    for (int c = 0; c < CCH; c++)
        s[tid * 129 + c] = tf32r(s[tid * 129 + c] * scale);
    __syncthreads();

    float4* dst = (float4*)(g_imgT + (size_t)blockIdx.x * TILE_FLOATS);
    #pragma unroll 1
    for (int k8 = 0; k8 < 16; k8++) {
        #pragma unroll
        for (int s2 = 0; s2 < 2; s2++) {
            int slot = tid + s2 * 128;           // m16(3b) | lane(5b)
            int m16 = slot >> 5, lane = slot & 31;
            int r0 = m16 * 16 + (lane >> 2), r1 = r0 + 8;
            int c0 = k8 * 8 + (lane & 3), c1 = c0 + 4;
            float4 w = make_float4(s[r0 * 129 + c0], s[r1 * 129 + c0],
                                   s[r0 * 129 + c1], s[r1 * 129 + c1]);
            dst[(m16 * 16 + k8) * 32 + lane] = w;
        }
    }
}

// ============================================================================
// K2: refs -> normalized tf32, B-fragment-linear. 576 blocks (bn*18+t) x 128.
// ============================================================================
__global__ __launch_bounds__(128) void k_prep_refs(const float* __restrict__ refs) {
    extern __shared__ float s[];                 // [128][129]
    const int tid = threadIdx.x;
    const int bn = blockIdx.x / NTILES;
    const int t  = blockIdx.x % NTILES;
    const int q = t * 128 + tid;
    const float* base = refs + (size_t)bn * CCH * HW + q;

    float ss = 0.f;
    #pragma unroll 8
    for (int c = 0; c < CCH; c++) {
        float v = base[(size_t)c * HW];
        s[tid * 129 + c] = v;
        ss += v * v;
    }
    float scale = 1.0f / fmaxf(sqrtf(ss), 1e-12f);
    #pragma unroll 8
    for (int c = 0; c < CCH; c++)
        s[tid * 129 + c] = tf32r(s[tid * 129 + c] * scale);
    __syncthreads();

    float2* dst = (float2*)(g_refsT + (size_t)blockIdx.x * TILE_FLOATS);
    #pragma unroll 1
    for (int k8 = 0; k8 < 16; k8++) {
        #pragma unroll
        for (int s2 = 0; s2 < 4; s2++) {
            int slot = tid + s2 * 128;           // n8(4b) | lane(5b)
            int n8 = slot >> 5, lane = slot & 31;
            int row = n8 * 8 + (lane >> 2);
            int c0 = k8 * 8 + (lane & 3), c1 = c0 + 4;
            float2 w = make_float2(s[row * 129 + c0], s[row * 129 + c1]);
            dst[(n8 * 16 + k8) * 32 + lane] = w;
        }
    }
}

// ============================================================================
// K3: main GEMM+max. CTA=(bm,bn). A resident, B double-buffered cp.async.
// 8 warps 4(M)x2(N), warp tile 32x64. Frag loads: LDS.128(A)/LDS.64(B),
// fully coalesced (fragment-linear layout). Row max in registers.
// ============================================================================
__device__ __forceinline__ void fill_tile_async(uint32_t dst,
                                                const float* __restrict__ src,
                                                int tid) {
    const char* s = (const char*)src;
    #pragma unroll
    for (int i = 0; i < 16; i++)
        CP_ASYNC16(dst + i * 4096 + tid * 16, s + i * 4096 + tid * 16);
}

__global__ __launch_bounds__(256, 1) void k_gemm_max() {
    extern __shared__ char sm[];
    const int tid = threadIdx.x, wid = tid >> 5, lane = tid & 31;
    const int wm = wid >> 1, wn = wid & 1;
    const uint32_t sbase = smem_u32(sm);
    const uint32_t Abase = sbase;
    const uint32_t Bbuf0 = sbase + TILE_BYTES;
    const uint32_t Bbuf1 = sbase + 2 * TILE_BYTES;

    const int bm = blockIdx.x % MTILES;
    const int bn = blockIdx.x / MTILES;
    const int p0 = bm * MT;
    const float* refT = g_refsT + (size_t)bn * NTILES * TILE_FLOATS;

    fill_tile_async(Abase, g_imgT + (size_t)bm * TILE_FLOATS, tid);
    fill_tile_async(Bbuf0, refT, tid);
    CP_COMMIT();

    // frag base addresses (bytes):
    // a(mf,ks) = Abase + ((wm*2+mf)*16 + ks)*512 + lane*16
    // b(nf,ks) = Bbase + ((wn*8+nf)*16 + ks)*256 + lane*8
    const uint32_t aAddr0 = Abase + (uint32_t)(wm * 2 * 16) * 512 + lane * 16;
    const uint32_t bOffW  = (uint32_t)(wn * 8 * 16) * 256 + lane * 8;

    float rm0[2], rm1[2];
    #pragma unroll
    for (int mf = 0; mf < 2; mf++) {
        rm0[mf] = __uint_as_float(0xff800000u);
        rm1[mf] = __uint_as_float(0xff800000u);
    }

    for (int t = 0; t < NTILES; t++) {
        CP_WAIT0();
        __syncthreads();

        if (t + 1 < NTILES) {
            uint32_t nb = ((t + 1) & 1) ? Bbuf1 : Bbuf0;
            fill_tile_async(nb, refT + (size_t)(t + 1) * TILE_FLOATS, tid);
            CP_COMMIT();
        }

        const uint32_t Bb = ((t & 1) ? Bbuf1 : Bbuf0) + bOffW;

        float acc[2][8][4];
        #pragma unroll
        for (int i = 0; i < 2; i++)
            #pragma unroll
            for (int j = 0; j < 8; j++)
                #pragma unroll
                for (int k = 0; k < 4; k++) acc[i][j][k] = 0.f;

        #pragma unroll
        for (int ks = 0; ks < 16; ks++) {
            uint32_t a[2][4], b[8][2];
            #pragma unroll
            for (int mf = 0; mf < 2; mf++)
                asm volatile("ld.shared.v4.b32 {%0,%1,%2,%3}, [%4];"
                             : "=r"(a[mf][0]), "=r"(a[mf][1]),
                               "=r"(a[mf][2]), "=r"(a[mf][3])
                             : "r"(aAddr0 + (uint32_t)(mf * 16 + ks) * 512));
            #pragma unroll
            for (int nf = 0; nf < 8; nf++)
                asm volatile("ld.shared.v2.b32 {%0,%1}, [%2];"
                             : "=r"(b[nf][0]), "=r"(b[nf][1])
                             : "r"(Bb + (uint32_t)(nf * 16 + ks) * 256));
            #pragma unroll
            for (int mf = 0; mf < 2; mf++)
                #pragma unroll
                for (int nf = 0; nf < 8; nf++)
                    mma_tf32(acc[mf][nf], a[mf], b[nf]);
        }

        #pragma unroll
        for (int mf = 0; mf < 2; mf++)
            #pragma unroll
            for (int nf = 0; nf < 8; nf++) {
                rm0[mf] = fmaxf(rm0[mf], fmaxf(acc[mf][nf][0], acc[mf][nf][1]));
                rm1[mf] = fmaxf(rm1[mf], fmaxf(acc[mf][nf][2], acc[mf][nf][3]));
            }
    }

    // final epilogue: reduce 4 lanes sharing a row, then one atomic per row
    #pragma unroll
    for (int mf = 0; mf < 2; mf++) {
        float m0 = rm0[mf], m1 = rm1[mf];
        m0 = fmaxf(m0, __shfl_xor_sync(0xffffffffu, m0, 1));
        m0 = fmaxf(m0, __shfl_xor_sync(0xffffffffu, m0, 2));
        m1 = fmaxf(m1, __shfl_xor_sync(0xffffffffu, m1, 1));
        m1 = fmaxf(m1, __shfl_xor_sync(0xffffffffu, m1, 2));
        if ((lane & 3) == 0) {
            int row = p0 + wm * 32 + mf * 16 + (lane >> 2);
            atomicMax(&g_pmax[row], fkey(m0));
            atomicMax(&g_pmax[row + 8], fkey(m1));
        }
    }
}

// ============================================================================
// K4: decode keys to floats into d_out
// ============================================================================
__global__ void k_final(float* __restrict__ out) {
    int p = blockIdx.x * blockDim.x + threadIdx.x;
    if (p < HW) out[p] = finv(g_pmax[p]);
}

// ============================================================================
extern "C" void kernel_launch(void* const* d_in, const int* in_sizes, int n_in,
                              void* d_out, int out_size) {
    const float* refs = (const float*)d_in[0];
    const float* img  = (const float*)d_in[1];
    float* out = (float*)d_out;

    cudaFuncSetAttribute(k_gemm_max, cudaFuncAttributeMaxDynamicSharedMemorySize,
                         DSMEM_GEMM);
    cudaFuncSetAttribute(k_prep_img, cudaFuncAttributeMaxDynamicSharedMemorySize,
                         DSMEM_PREP);
    cudaFuncSetAttribute(k_prep_refs, cudaFuncAttributeMaxDynamicSharedMemorySize,
                         DSMEM_PREP);

    k_init<<<(HW + 255) / 256, 256>>>();
    k_prep_img<<<MTILES, 128, DSMEM_PREP>>>(img);
    k_prep_refs<<<NREF * NTILES, 128, DSMEM_PREP>>>(refs);
    k_gemm_max<<<NBLK, 256, DSMEM_GEMM>>>();
    k_final<<<(HW + 255) / 256, 256>>>(out);
}

// round 6
// speedup vs baseline: 2.1534x; 1.2054x over previous
#include <cuda_runtime.h>
#include <cstdint>

// ============================================================================
// PuzzleSim: out[p] = max over (n,q) of <img_n[:,p], refs_n[n,:,q]>
// R6: int8 IMMA m16n8k32 3-pass split.
//   v ~ (128*hi + lo)/2^14, |hi|<=127, |lo|<=64.
//   S = 128*Sum(hi*hi) + Sum(hi*lo + lo*hi); sim ~ S/2^21 (lo*lo dropped,
//   ~6e-5 abs err). Integer accum/max -> exact, monotone.
// A-hi frags in registers (whole kernel), A-lo in smem, B streamed via
// 3-stage cp.async ring. All operands fragment-linear (contiguous LDS.128).
// ============================================================================

#define NREF    32
#define CCH     128
#define HW      2304            // 48*48
#define MT      128
#define NT      128
#define NTILES  (HW / NT)       // 18
#define MTILES  (HW / MT)       // 18
#define NBLK    (MTILES * NREF) // 576
#define TILE_U32 8192           // one (hi+lo) frag-linear tile = 32KB
#define BSTAGE_BYTES 32768
#define ALO_BYTES    16384
#define DSMEM_GEMM (ALO_BYTES + 3 * BSTAGE_BYTES)   // 112KB
#define PREP_SMEM  (2 * 128 * 132)                  // 33792B

// ---- device scratch ----
// per-tile layout (u32): [pass(2)][blk(8)][ks(4)][lane(32)][reg(4)]
//   A: blk = m16 index (8 x 16 rows);  B: blk = nf-pair (8 x 16 cols)
__device__ uint32_t g_imgA[(size_t)MTILES * TILE_U32];
__device__ uint32_t g_refsQ[(size_t)NBLK * TILE_U32];
__device__ int g_pmax[HW];

// ============================================================================
// helpers
// ============================================================================
__device__ __forceinline__ uint32_t smem_u32(const void* p) {
    uint32_t a;
    asm("{ .reg .u64 t; cvta.to.shared.u64 t, %1; cvt.u32.u64 %0, t; }"
        : "=r"(a) : "l"(p));
    return a;
}
__device__ __forceinline__ void mma_s8(int* c, const uint32_t* a,
                                       const uint32_t* b) {
    asm volatile(
        "mma.sync.aligned.m16n8k32.row.col.s32.s8.s8.s32 "
        "{%0,%1,%2,%3}, {%4,%5,%6,%7}, {%8,%9}, {%0,%1,%2,%3};"
        : "+r"(c[0]), "+r"(c[1]), "+r"(c[2]), "+r"(c[3])
        : "r"(a[0]), "r"(a[1]), "r"(a[2]), "r"(a[3]), "r"(b[0]), "r"(b[1]));
}
#define CP_ASYNC16(dst, src) \
    asm volatile("cp.async.cg.shared.global [%0], [%1], 16;" \
                 :: "r"(dst), "l"(src) : "memory")
#define CP_COMMIT()  asm volatile("cp.async.commit_group;" ::: "memory")
#define CP_WAIT(n)   asm volatile("cp.async.wait_group %0;" :: "n"(n) : "memory")
#define LDS128(r0, r1, r2, r3, addr) \
    asm volatile("ld.shared.v4.b32 {%0,%1,%2,%3}, [%4];" \
                 : "=r"(r0), "=r"(r1), "=r"(r2), "=r"(r3) : "r"(addr))

// quantize a normalized value: q = round(v*2^14), hi=(q+64)>>7, lo=q-128*hi
__device__ __forceinline__ void quant14(float v, char& hi, char& lo) {
    int q = __float2int_rn(v * 16384.f);
    q = max(min(q, 16319), -16319);
    int h = (q + 64) >> 7;
    hi = (char)h;
    lo = (char)(q - (h << 7));
}

// ============================================================================
// K0: init int max keys
// ============================================================================
__global__ void k_init() {
    int p = blockIdx.x * blockDim.x + threadIdx.x;
    if (p < HW) g_pmax[p] = (int)0x80000000;
}

// ============================================================================
// K1: img -> normalized int8 hi/lo, A-fragment-linear. 18 blocks x 128 thr.
// thread = tile row (img position). smem: sh/sl [128][132] bytes.
// A frag mapping (m16n8k32 s8): reg0:(r, k) reg1:(r+8, k) reg2:(r, k+16)
// reg3:(r+8, k+16), r = lane>>2, k = 4*(lane&3) (+32*ks).
// ============================================================================
__global__ __launch_bounds__(128) void k_prep_img(const float* __restrict__ img) {
    extern __shared__ char sc[];
    char* sh = sc;
    char* sl = sc + 128 * 132;
    const int tid = threadIdx.x;
    const int p = blockIdx.x * 128 + tid;

    float v[CCH];
    float ss = 0.f;
    #pragma unroll 8
    for (int c = 0; c < CCH; c++) { v[c] = img[c * HW + p]; ss += v[c] * v[c]; }
    float scale = 1.0f / fmaxf(sqrtf(ss), 1e-12f);
    #pragma unroll 8
    for (int c = 0; c < CCH; c++) {
        char h, l;
        quant14(v[c] * scale, h, l);
        sh[tid * 132 + c] = h;
        sl[tid * 132 + c] = l;
    }
    __syncthreads();

    uint32_t* dst = g_imgA + (size_t)blockIdx.x * TILE_U32;
    #pragma unroll 4
    for (int w = 0; w < 64; w++) {
        int idx = w * 128 + tid;
        int reg = idx & 3, lane = (idx >> 2) & 31, ks = (idx >> 7) & 3;
        int m16 = (idx >> 9) & 7, pass = idx >> 12;
        int row = 16 * m16 + (lane >> 2) + 8 * (reg & 1);
        int k = 32 * ks + 4 * (lane & 3) + 16 * (reg >> 1);
        const char* s = pass ? sl : sh;
        dst[idx] = *(const uint32_t*)(s + row * 132 + k);
    }
}

// ============================================================================
// K2: refs -> int8 hi/lo, B-fragment-linear. 576 blocks (bn*18+t) x 128 thr.
// thread = tile col (ref position q). B frag (col-major): reg pair layout
// r0:(col0,k) r1:(col0,k+16) r2:(col0+8,k) r3:(col0+8,k+16),
// col0 = 16*nfp + lane>>2, k = 4*(lane&3) (+32*ks).
// ============================================================================
__global__ __launch_bounds__(128) void k_prep_refs(const float* __restrict__ refs) {
    extern __shared__ char sc[];
    char* sh = sc;
    char* sl = sc + 128 * 132;
    const int tid = threadIdx.x;
    const int bn = blockIdx.x / NTILES;
    const int t  = blockIdx.x % NTILES;
    const int q = t * 128 + tid;
    const float* base = refs + (size_t)bn * CCH * HW + q;

    float v[CCH];
    float ss = 0.f;
    #pragma unroll 8
    for (int c = 0; c < CCH; c++) {
        v[c] = base[(size_t)c * HW];
        ss += v[c] * v[c];
    }
    float scale = 1.0f / fmaxf(sqrtf(ss), 1e-12f);
    #pragma unroll 8
    for (int c = 0; c < CCH; c++) {
        char h, l;
        quant14(v[c] * scale, h, l);
        sh[tid * 132 + c] = h;
        sl[tid * 132 + c] = l;
    }
    __syncthreads();

    uint32_t* dst = g_refsQ + (size_t)blockIdx.x * TILE_U32;
    #pragma unroll 4
    for (int w = 0; w < 64; w++) {
        int idx = w * 128 + tid;
        int reg = idx & 3, lane = (idx >> 2) & 31, ks = (idx >> 7) & 3;
        int nfp = (idx >> 9) & 7, pass = idx >> 12;
        int col = 16 * nfp + (lane >> 2) + 8 * (reg >> 1);
        int k = 32 * ks + 4 * (lane & 3) + 16 * (reg & 1);
        const char* s = pass ? sl : sh;
        dst[idx] = *(const uint32_t*)(s + col * 132 + k);
    }
}

// ============================================================================
// K3: main GEMM+max. CTA=(bm,bn). 256 thr, 8 warps 4(M)x2(N), warp 32x64.
// A-hi in regs (LDG once), A-lo in smem, B 3-stage cp.async ring.
// Integer accumulate: S = 128*hh + xx; int row-max in regs; atomicMax(s32).
// ============================================================================
__device__ __forceinline__ void fill_b_async(uint32_t dst,
                                             const uint32_t* __restrict__ src,
                                             int tid) {
    const char* s = (const char*)src;
    #pragma unroll
    for (int i = 0; i < 8; i++)
        CP_ASYNC16(dst + i * 4096 + tid * 16, s + i * 4096 + tid * 16);
}

__global__ __launch_bounds__(256, 1) void k_gemm_max() {
    extern __shared__ char sm[];
    const int tid = threadIdx.x, wid = tid >> 5, lane = tid & 31;
    const int wm = wid >> 1, wn = wid & 1;
    const uint32_t sbase = smem_u32(sm);
    const uint32_t AloS = sbase;                 // 16KB
    const uint32_t Bring = sbase + ALO_BYTES;    // 3 x 32KB

    const int bm = blockIdx.x % MTILES;
    const int bn = blockIdx.x / MTILES;
    const int p0 = bm * MT;
    const uint32_t* imgT = g_imgA + (size_t)bm * TILE_U32;
    const uint32_t* refT = g_refsQ + (size_t)(bn * NTILES) * TILE_U32;

    // prologue: A-lo + B0 (group0), B1 (group1)
    {
        const char* asrc = (const char*)(imgT + 4096);   // pass1 = lo, 16KB
        #pragma unroll
        for (int i = 0; i < 4; i++)
            CP_ASYNC16(AloS + i * 4096 + tid * 16, asrc + i * 4096 + tid * 16);
        fill_b_async(Bring, refT, tid);
        CP_COMMIT();
        fill_b_async(Bring + BSTAGE_BYTES, refT + TILE_U32, tid);
        CP_COMMIT();
    }

    // A-hi fragments -> registers (live whole kernel)
    uint32_t ahi[2][4][4];
    #pragma unroll
    for (int mf = 0; mf < 2; mf++)
        #pragma unroll
        for (int ks = 0; ks < 4; ks++) {
            const uint4 w = *(const uint4*)(imgT +
                (size_t)(((wm * 2 + mf) * 4 + ks) * 32 + lane) * 4);
            ahi[mf][ks][0] = w.x; ahi[mf][ks][1] = w.y;
            ahi[mf][ks][2] = w.z; ahi[mf][ks][3] = w.w;
        }

    // per-warp smem frag base offsets
    const uint32_t aloOff = AloS + (uint32_t)(wm * 2 * 4 * 32 + lane) * 16;
    const uint32_t bOffW  = (uint32_t)((wn * 4) * 4 * 32 + lane) * 16;

    int rmax0[2], rmax1[2];
    #pragma unroll
    for (int mf = 0; mf < 2; mf++) { rmax0[mf] = (int)0x80000000; rmax1[mf] = (int)0x80000000; }

    for (int t = 0; t < NTILES; t++) {
        CP_WAIT(1);                      // stage t resident
        __syncthreads();

        if (t + 2 < NTILES) {
            fill_b_async(Bring + (uint32_t)((t + 2) % 3) * BSTAGE_BYTES,
                         refT + (size_t)(t + 2) * TILE_U32, tid);
            CP_COMMIT();
        }

        const uint32_t Bhi = Bring + (uint32_t)(t % 3) * BSTAGE_BYTES + bOffW;
        const uint32_t Blo = Bhi + 16384;

        int hh[2][8][4], xx[2][8][4];
        #pragma unroll
        for (int mf = 0; mf < 2; mf++)
            #pragma unroll
            for (int nf = 0; nf < 8; nf++)
                #pragma unroll
                for (int e = 0; e < 4; e++) { hh[mf][nf][e] = 0; xx[mf][nf][e] = 0; }

        #pragma unroll
        for (int ks = 0; ks < 4; ks++) {
            uint32_t alo[2][4];
            #pragma unroll
            for (int mf = 0; mf < 2; mf++)
                LDS128(alo[mf][0], alo[mf][1], alo[mf][2], alo[mf][3],
                       aloOff + (uint32_t)((mf * 4 + ks) * 32) * 16);
            #pragma unroll
            for (int np = 0; np < 4; np++) {
                const uint32_t fo = (uint32_t)((np * 4 + ks) * 32) * 16;
                uint32_t bh[4], bl[4];
                LDS128(bh[0], bh[1], bh[2], bh[3], Bhi + fo);
                LDS128(bl[0], bl[1], bl[2], bl[3], Blo + fo);
                #pragma unroll
                for (int half = 0; half < 2; half++) {
                    const int nf = np * 2 + half;
                    const uint32_t* bhp = bh + 2 * half;
                    const uint32_t* blp = bl + 2 * half;
                    #pragma unroll
                    for (int mf = 0; mf < 2; mf++) {
                        mma_s8(hh[mf][nf], ahi[mf][ks], bhp);
                        mma_s8(xx[mf][nf], ahi[mf][ks], blp);
                        mma_s8(xx[mf][nf], alo[mf],     bhp);
                    }
                }
            }
        }

        // integer fold: S = 128*hh + xx, running row max
        #pragma unroll
        for (int mf = 0; mf < 2; mf++)
            #pragma unroll
            for (int nf = 0; nf < 8; nf++) {
                int s0 = hh[mf][nf][0] * 128 + xx[mf][nf][0];
                int s1 = hh[mf][nf][1] * 128 + xx[mf][nf][1];
                int s2 = hh[mf][nf][2] * 128 + xx[mf][nf][2];
                int s3 = hh[mf][nf][3] * 128 + xx[mf][nf][3];
                rmax0[mf] = max(rmax0[mf], max(s0, s1));
                rmax1[mf] = max(rmax1[mf], max(s2, s3));
            }
    }

    // final: reduce 4 lanes sharing a row, one atomic per row
    #pragma unroll
    for (int mf = 0; mf < 2; mf++) {
        int m0 = rmax0[mf], m1 = rmax1[mf];
        m0 = max(m0, __shfl_xor_sync(0xffffffffu, m0, 1));
        m0 = max(m0, __shfl_xor_sync(0xffffffffu, m0, 2));
        m1 = max(m1, __shfl_xor_sync(0xffffffffu, m1, 1));
        m1 = max(m1, __shfl_xor_sync(0xffffffffu, m1, 2));
        if ((lane & 3) == 0) {
            int row = p0 + wm * 32 + mf * 16 + (lane >> 2);
            atomicMax(&g_pmax[row], m0);
            atomicMax(&g_pmax[row + 8], m1);
        }
    }
}

// ============================================================================
// K4: decode int keys: sim = S / 2^21
// ============================================================================
__global__ void k_final(float* __restrict__ out) {
    int p = blockIdx.x * blockDim.x + threadIdx.x;
    if (p < HW) out[p] = (float)g_pmax[p] * (1.0f / 2097152.0f);
}

// ============================================================================
extern "C" void kernel_launch(void* const* d_in, const int* in_sizes, int n_in,
                              void* d_out, int out_size) {
    const float* refs = (const float*)d_in[0];
    const float* img  = (const float*)d_in[1];
    float* out = (float*)d_out;

    cudaFuncSetAttribute(k_gemm_max, cudaFuncAttributeMaxDynamicSharedMemorySize,
                         DSMEM_GEMM);

    k_init<<<(HW + 255) / 256, 256>>>();
    k_prep_img<<<MTILES, 128, PREP_SMEM>>>(img);
    k_prep_refs<<<NREF * NTILES, 128, PREP_SMEM>>>(refs);
    k_gemm_max<<<NBLK, 256, DSMEM_GEMM>>>();
    k_final<<<(HW + 255) / 256, 256>>>(out);
}

// round 7
// speedup vs baseline: 2.3720x; 1.1015x over previous
#include <cuda_runtime.h>
#include <cstdint>

// ============================================================================
// PuzzleSim: out[p] = max over (n,q) of <img_n[:,p], refs_n[n,:,q]>
// R7: int8 IMMA 3-pass split, restructured for 2 CTAs/SM:
//  - np-outer/ks-inner loop: accum live range 128 -> 32 regs, fold overlaps mma
//  - A hi AND lo fragments in registers (64 regs, loaded once)
//  - smem = 3-stage B ring only (96KB) -> 2 CTAs/SM, waves 3.89 -> 1.95
// S = 128*Sum(hi*hi) + Sum(hi*lo + lo*hi); sim ~ S/2^21; integer row-max.
// ============================================================================

#define NREF    32
#define CCH     128
#define HW      2304            // 48*48
#define MT      128
#define NT      128
#define NTILES  (HW / NT)       // 18
#define MTILES  (HW / MT)       // 18
#define NBLK    (MTILES * NREF) // 576
#define TILE_U32 8192           // one (hi+lo) frag-linear tile = 32KB
#define BSTAGE_BYTES 32768
#define DSMEM_GEMM (3 * BSTAGE_BYTES)   // 96KB -> 2 CTAs/SM
#define PREP_SMEM  (2 * 128 * 132)      // 33792B

// ---- device scratch ----
// per-tile layout (u32): [pass(2)][blk(8)][ks(4)][lane(32)][reg(4)]
//   A: blk = m16 index (8 x 16 rows);  B: blk = nf-pair (8 x 16 cols)
__device__ uint32_t g_imgA[(size_t)MTILES * TILE_U32];
__device__ uint32_t g_refsQ[(size_t)NBLK * TILE_U32];
__device__ int g_pmax[HW];

// ============================================================================
// helpers
// ============================================================================
__device__ __forceinline__ uint32_t smem_u32(const void* p) {
    uint32_t a;
    asm("{ .reg .u64 t; cvta.to.shared.u64 t, %1; cvt.u32.u64 %0, t; }"
        : "=r"(a) : "l"(p));
    return a;
}
__device__ __forceinline__ void mma_s8(int* c, const uint32_t* a,
                                       const uint32_t* b) {
    asm volatile(
        "mma.sync.aligned.m16n8k32.row.col.s32.s8.s8.s32 "
        "{%0,%1,%2,%3}, {%4,%5,%6,%7}, {%8,%9}, {%0,%1,%2,%3};"
        : "+r"(c[0]), "+r"(c[1]), "+r"(c[2]), "+r"(c[3])
        : "r"(a[0]), "r"(a[1]), "r"(a[2]), "r"(a[3]), "r"(b[0]), "r"(b[1]));
}
#define CP_ASYNC16(dst, src) \
    asm volatile("cp.async.cg.shared.global [%0], [%1], 16;" \
                 :: "r"(dst), "l"(src) : "memory")
#define CP_COMMIT()  asm volatile("cp.async.commit_group;" ::: "memory")
#define CP_WAIT(n)   asm volatile("cp.async.wait_group %0;" :: "n"(n) : "memory")
#define LDS128(r0, r1, r2, r3, addr) \
    asm volatile("ld.shared.v4.b32 {%0,%1,%2,%3}, [%4];" \
                 : "=r"(r0), "=r"(r1), "=r"(r2), "=r"(r3) : "r"(addr))

// quantize a normalized value: q = round(v*2^14), hi=(q+64)>>7, lo=q-128*hi
__device__ __forceinline__ void quant14(float v, char& hi, char& lo) {
    int q = __float2int_rn(v * 16384.f);
    q = max(min(q, 16319), -16319);
    int h = (q + 64) >> 7;
    hi = (char)h;
    lo = (char)(q - (h << 7));
}

// ============================================================================
// K1: img -> normalized int8 hi/lo, A-fragment-linear; also inits g_pmax
// (18 blocks x 128 thr = 2304 = HW threads exactly).
// ============================================================================
__global__ __launch_bounds__(128) void k_prep_img(const float* __restrict__ img) {
    extern __shared__ char sc[];
    char* sh = sc;
    char* sl = sc + 128 * 132;
    const int tid = threadIdx.x;
    const int p = blockIdx.x * 128 + tid;

    g_pmax[p] = (int)0x80000000;

    float v[CCH];
    float ss = 0.f;
    #pragma unroll 8
    for (int c = 0; c < CCH; c++) { v[c] = img[c * HW + p]; ss += v[c] * v[c]; }
    float scale = 1.0f / fmaxf(sqrtf(ss), 1e-12f);
    #pragma unroll 8
    for (int c = 0; c < CCH; c++) {
        char h, l;
        quant14(v[c] * scale, h, l);
        sh[tid * 132 + c] = h;
        sl[tid * 132 + c] = l;
    }
    __syncthreads();

    uint32_t* dst = g_imgA + (size_t)blockIdx.x * TILE_U32;
    #pragma unroll 4
    for (int w = 0; w < 64; w++) {
        int idx = w * 128 + tid;
        int reg = idx & 3, lane = (idx >> 2) & 31, ks = (idx >> 7) & 3;
        int m16 = (idx >> 9) & 7, pass = idx >> 12;
        int row = 16 * m16 + (lane >> 2) + 8 * (reg & 1);
        int k = 32 * ks + 4 * (lane & 3) + 16 * (reg >> 1);
        const char* s = pass ? sl : sh;
        dst[idx] = *(const uint32_t*)(s + row * 132 + k);
    }
}

// ============================================================================
// K2: refs -> int8 hi/lo, B-fragment-linear. 576 blocks (bn*18+t) x 128 thr.
// ============================================================================
__global__ __launch_bounds__(128) void k_prep_refs(const float* __restrict__ refs) {
    extern __shared__ char sc[];
    char* sh = sc;
    char* sl = sc + 128 * 132;
    const int tid = threadIdx.x;
    const int bn = blockIdx.x / NTILES;
    const int t  = blockIdx.x % NTILES;
    const int q = t * 128 + tid;
    const float* base = refs + (size_t)bn * CCH * HW + q;

    float v[CCH];
    float ss = 0.f;
    #pragma unroll 8
    for (int c = 0; c < CCH; c++) {
        v[c] = base[(size_t)c * HW];
        ss += v[c] * v[c];
    }
    float scale = 1.0f / fmaxf(sqrtf(ss), 1e-12f);
    #pragma unroll 8
    for (int c = 0; c < CCH; c++) {
        char h, l;
        quant14(v[c] * scale, h, l);
        sh[tid * 132 + c] = h;
        sl[tid * 132 + c] = l;
    }
    __syncthreads();

    uint32_t* dst = g_refsQ + (size_t)blockIdx.x * TILE_U32;
    #pragma unroll 4
    for (int w = 0; w < 64; w++) {
        int idx = w * 128 + tid;
        int reg = idx & 3, lane = (idx >> 2) & 31, ks = (idx >> 7) & 3;
        int nfp = (idx >> 9) & 7, pass = idx >> 12;
        int col = 16 * nfp + (lane >> 2) + 8 * (reg >> 1);
        int k = 32 * ks + 4 * (lane & 3) + 16 * (reg & 1);
        const char* s = pass ? sl : sh;
        dst[idx] = *(const uint32_t*)(s + col * 132 + k);
    }
}

// ============================================================================
// K3: main GEMM+max. CTA=(bm,bn), 2 CTAs/SM. 8 warps 4(M)x2(N), warp 32x64.
// A hi+lo in regs; B 3-stage cp.async ring. np-outer loop: fold each np-group
// right after its mmas so accum regs stay at 32 and fold overlaps tensor work.
// ============================================================================
__device__ __forceinline__ void fill_b_async(uint32_t dst,
                                             const uint32_t* __restrict__ src,
                                             int tid) {
    const char* s = (const char*)src;
    #pragma unroll
    for (int i = 0; i < 8; i++)
        CP_ASYNC16(dst + i * 4096 + tid * 16, s + i * 4096 + tid * 16);
}

__global__ __launch_bounds__(256, 2) void k_gemm_max() {
    extern __shared__ char sm[];
    const int tid = threadIdx.x, wid = tid >> 5, lane = tid & 31;
    const int wm = wid >> 1, wn = wid & 1;
    const uint32_t Bring = smem_u32(sm);         // 3 x 32KB

    const int bm = blockIdx.x % MTILES;
    const int bn = blockIdx.x / MTILES;
    const int p0 = bm * MT;
    const uint32_t* imgT = g_imgA + (size_t)bm * TILE_U32;
    const uint32_t* refT = g_refsQ + (size_t)(bn * NTILES) * TILE_U32;

    // prologue: B0 (group0), B1 (group1)
    fill_b_async(Bring, refT, tid);
    CP_COMMIT();
    fill_b_async(Bring + BSTAGE_BYTES, refT + TILE_U32, tid);
    CP_COMMIT();

    // A hi+lo fragments -> registers (live whole kernel)
    uint32_t ahi[2][4][4], alo[2][4][4];
    #pragma unroll
    for (int mf = 0; mf < 2; mf++)
        #pragma unroll
        for (int ks = 0; ks < 4; ks++) {
            const size_t fi = (size_t)(((wm * 2 + mf) * 4 + ks) * 32 + lane) * 4;
            const uint4 wh = *(const uint4*)(imgT + fi);
            const uint4 wl = *(const uint4*)(imgT + 4096 + fi);
            ahi[mf][ks][0] = wh.x; ahi[mf][ks][1] = wh.y;
            ahi[mf][ks][2] = wh.z; ahi[mf][ks][3] = wh.w;
            alo[mf][ks][0] = wl.x; alo[mf][ks][1] = wl.y;
            alo[mf][ks][2] = wl.z; alo[mf][ks][3] = wl.w;
        }

    const uint32_t bOffW = (uint32_t)((wn * 4) * 4 * 32 + lane) * 16;

    int rmax0[2], rmax1[2];
    #pragma unroll
    for (int mf = 0; mf < 2; mf++) { rmax0[mf] = (int)0x80000000; rmax1[mf] = (int)0x80000000; }

    for (int t = 0; t < NTILES; t++) {
        CP_WAIT(1);                      // stage t resident
        __syncthreads();

        if (t + 2 < NTILES) {
            fill_b_async(Bring + (uint32_t)((t + 2) % 3) * BSTAGE_BYTES,
                         refT + (size_t)(t + 2) * TILE_U32, tid);
            CP_COMMIT();
        }

        const uint32_t Bhi = Bring + (uint32_t)(t % 3) * BSTAGE_BYTES + bOffW;
        const uint32_t Blo = Bhi + 16384;

        #pragma unroll
        for (int np = 0; np < 4; np++) {
            int hh[2][2][4], xx[2][2][4];
            #pragma unroll
            for (int mf = 0; mf < 2; mf++)
                #pragma unroll
                for (int h = 0; h < 2; h++)
                    #pragma unroll
                    for (int e = 0; e < 4; e++) { hh[mf][h][e] = 0; xx[mf][h][e] = 0; }

            #pragma unroll
            for (int ks = 0; ks < 4; ks++) {
                const uint32_t fo = (uint32_t)((np * 4 + ks) * 32) * 16;
                uint32_t bh[4], bl[4];
                LDS128(bh[0], bh[1], bh[2], bh[3], Bhi + fo);
                LDS128(bl[0], bl[1], bl[2], bl[3], Blo + fo);
                #pragma unroll
                for (int half = 0; half < 2; half++) {
                    const uint32_t* bhp = bh + 2 * half;
                    const uint32_t* blp = bl + 2 * half;
                    #pragma unroll
                    for (int mf = 0; mf < 2; mf++) {
                        mma_s8(hh[mf][half], ahi[mf][ks], bhp);
                        mma_s8(xx[mf][half], ahi[mf][ks], blp);
                        mma_s8(xx[mf][half], alo[mf][ks], bhp);
                    }
                }
            }

            // fold this np-group (overlaps next group's tensor work)
            #pragma unroll
            for (int mf = 0; mf < 2; mf++)
                #pragma unroll
                for (int h = 0; h < 2; h++) {
                    int s0 = hh[mf][h][0] * 128 + xx[mf][h][0];
                    int s1 = hh[mf][h][1] * 128 + xx[mf][h][1];
                    int s2 = hh[mf][h][2] * 128 + xx[mf][h][2];
                    int s3 = hh[mf][h][3] * 128 + xx[mf][h][3];
                    rmax0[mf] = max(rmax0[mf], max(s0, s1));
                    rmax1[mf] = max(rmax1[mf], max(s2, s3));
                }
        }
    }

    // final: reduce 4 lanes sharing a row, one atomic per row
    #pragma unroll
    for (int mf = 0; mf < 2; mf++) {
        int m0 = rmax0[mf], m1 = rmax1[mf];
        m0 = max(m0, __shfl_xor_sync(0xffffffffu, m0, 1));
        m0 = max(m0, __shfl_xor_sync(0xffffffffu, m0, 2));
        m1 = max(m1, __shfl_xor_sync(0xffffffffu, m1, 1));
        m1 = max(m1, __shfl_xor_sync(0xffffffffu, m1, 2));
        if ((lane & 3) == 0) {
            int row = p0 + wm * 32 + mf * 16 + (lane >> 2);
            atomicMax(&g_pmax[row], m0);
            atomicMax(&g_pmax[row + 8], m1);
        }
    }
}

// ============================================================================
// K4: decode int keys: sim = S / 2^21
// ============================================================================
__global__ void k_final(float* __restrict__ out) {
    int p = blockIdx.x * blockDim.x + threadIdx.x;
    if (p < HW) out[p] = (float)g_pmax[p] * (1.0f / 2097152.0f);
}

// ============================================================================
extern "C" void kernel_launch(void* const* d_in, const int* in_sizes, int n_in,
                              void* d_out, int out_size) {
    const float* refs = (const float*)d_in[0];
    const float* img  = (const float*)d_in[1];
    float* out = (float*)d_out;

    cudaFuncSetAttribute(k_gemm_max, cudaFuncAttributeMaxDynamicSharedMemorySize,
                         DSMEM_GEMM);

    k_prep_img<<<MTILES, 128, PREP_SMEM>>>(img);
    k_prep_refs<<<NREF * NTILES, 128, PREP_SMEM>>>(refs);
    k_gemm_max<<<NBLK, 256, DSMEM_GEMM>>>();
    k_final<<<(HW + 255) / 256, 256>>>(out);
}

// round 8
// speedup vs baseline: 2.4117x; 1.0167x over previous
#include <cuda_runtime.h>
#include <cstdint>

// ============================================================================
// PuzzleSim: out[p] = max over (n,q) of <img_n[:,p], refs_n[n,:,q]>
// R8 = R7 (int8 IMMA 3-pass, 2 CTAs/SM, A in regs, 3-stage B ring) with the
// kernel graph collapsed: one fused prep launch, and the final decode fused
// into k_gemm via the last-block pattern (threadfence + atomic counter).
// S = 128*Sum(hi*hi) + Sum(hi*lo + lo*hi); sim ~ S/2^21; integer row-max.
// ============================================================================

#define NREF    32
#define CCH     128
#define HW      2304            // 48*48
#define MT      128
#define NT      128
#define NTILES  (HW / NT)       // 18
#define MTILES  (HW / MT)       // 18
#define NBLK    (MTILES * NREF) // 576
#define TILE_U32 8192           // one (hi+lo) frag-linear tile = 32KB
#define BSTAGE_BYTES 32768
#define DSMEM_GEMM (3 * BSTAGE_BYTES)   // 96KB -> 2 CTAs/SM
#define PREP_SMEM  (2 * 128 * 132)      // 33792B

// ---- device scratch ----
// per-tile layout (u32): [pass(2)][blk(8)][ks(4)][lane(32)][reg(4)]
//   A: blk = m16 index (8 x 16 rows);  B: blk = nf-pair (8 x 16 cols)
__device__ uint32_t g_imgA[(size_t)MTILES * TILE_U32];
__device__ uint32_t g_refsQ[(size_t)NBLK * TILE_U32];
__device__ int g_pmax[HW];
__device__ int g_done;

// ============================================================================
// helpers
// ============================================================================
__device__ __forceinline__ uint32_t smem_u32(const void* p) {
    uint32_t a;
    asm("{ .reg .u64 t; cvta.to.shared.u64 t, %1; cvt.u32.u64 %0, t; }"
        : "=r"(a) : "l"(p));
    return a;
}
__device__ __forceinline__ void mma_s8(int* c, const uint32_t* a,
                                       const uint32_t* b) {
    asm volatile(
        "mma.sync.aligned.m16n8k32.row.col.s32.s8.s8.s32 "
        "{%0,%1,%2,%3}, {%4,%5,%6,%7}, {%8,%9}, {%0,%1,%2,%3};"
        : "+r"(c[0]), "+r"(c[1]), "+r"(c[2]), "+r"(c[3])
        : "r"(a[0]), "r"(a[1]), "r"(a[2]), "r"(a[3]), "r"(b[0]), "r"(b[1]));
}
#define CP_ASYNC16(dst, src) \
    asm volatile("cp.async.cg.shared.global [%0], [%1], 16;" \
                 :: "r"(dst), "l"(src) : "memory")
#define CP_COMMIT()  asm volatile("cp.async.commit_group;" ::: "memory")
#define CP_WAIT(n)   asm volatile("cp.async.wait_group %0;" :: "n"(n) : "memory")
#define LDS128(r0, r1, r2, r3, addr) \
    asm volatile("ld.shared.v4.b32 {%0,%1,%2,%3}, [%4];" \
                 : "=r"(r0), "=r"(r1), "=r"(r2), "=r"(r3) : "r"(addr))

// quantize a normalized value: q = round(v*2^14), hi=(q+64)>>7, lo=q-128*hi
__device__ __forceinline__ void quant14(float v, char& hi, char& lo) {
    int q = __float2int_rn(v * 16384.f);
    q = max(min(q, 16319), -16319);
    int h = (q + 64) >> 7;
    hi = (char)h;
    lo = (char)(q - (h << 7));
}

// ============================================================================
// K1: fused prep. 594 blocks x 128 thr.
//   blocks [0,18):    img -> A-fragment-linear (+ g_pmax / g_done init)
//   blocks [18,594):  refs -> B-fragment-linear (bid-18 = bn*18 + t)
// ============================================================================
__global__ __launch_bounds__(128) void k_prep(const float* __restrict__ refs,
                                              const float* __restrict__ img) {
    extern __shared__ char sc[];
    char* sh = sc;
    char* sl = sc + 128 * 132;
    const int tid = threadIdx.x;
    const int bid = blockIdx.x;
    const bool is_img = bid < MTILES;

    const float* base;
    int stride;
    if (is_img) {
        const int p = bid * 128 + tid;
        g_pmax[p] = (int)0x80000000;
        if (p == 0) g_done = 0;
        base = img + p;
        stride = HW;
    } else {
        const int rb = bid - MTILES;
        const int bn = rb / NTILES;
        const int q = (rb % NTILES) * 128 + tid;
        base = refs + (size_t)bn * CCH * HW + q;
        stride = HW;
    }

    float v[CCH];
    float ss = 0.f;
    #pragma unroll 8
    for (int c = 0; c < CCH; c++) {
        v[c] = base[(size_t)c * stride];
        ss += v[c] * v[c];
    }
    float scale = 1.0f / fmaxf(sqrtf(ss), 1e-12f);
    #pragma unroll 8
    for (int c = 0; c < CCH; c++) {
        char h, l;
        quant14(v[c] * scale, h, l);
        sh[tid * 132 + c] = h;
        sl[tid * 132 + c] = l;
    }
    __syncthreads();

    if (is_img) {
        // A frag mapping: reg0:(r,k) reg1:(r+8,k) reg2:(r,k+16) reg3:(r+8,k+16)
        uint32_t* dst = g_imgA + (size_t)bid * TILE_U32;
        #pragma unroll 4
        for (int w = 0; w < 64; w++) {
            int idx = w * 128 + tid;
            int reg = idx & 3, lane = (idx >> 2) & 31, ks = (idx >> 7) & 3;
            int m16 = (idx >> 9) & 7, pass = idx >> 12;
            int row = 16 * m16 + (lane >> 2) + 8 * (reg & 1);
            int k = 32 * ks + 4 * (lane & 3) + 16 * (reg >> 1);
            const char* s = pass ? sl : sh;
            dst[idx] = *(const uint32_t*)(s + row * 132 + k);
        }
    } else {
        // B frag mapping: r0:(c0,k) r1:(c0,k+16) r2:(c0+8,k) r3:(c0+8,k+16)
        uint32_t* dst = g_refsQ + (size_t)(bid - MTILES) * TILE_U32;
        #pragma unroll 4
        for (int w = 0; w < 64; w++) {
            int idx = w * 128 + tid;
            int reg = idx & 3, lane = (idx >> 2) & 31, ks = (idx >> 7) & 3;
            int nfp = (idx >> 9) & 7, pass = idx >> 12;
            int col = 16 * nfp + (lane >> 2) + 8 * (reg >> 1);
            int k = 32 * ks + 4 * (lane & 3) + 16 * (reg & 1);
            const char* s = pass ? sl : sh;
            dst[idx] = *(const uint32_t*)(s + col * 132 + k);
        }
    }
}

// ============================================================================
// K2: main GEMM+max (+ fused final decode in the last CTA).
// CTA=(bm,bn), 2 CTAs/SM. 8 warps 4(M)x2(N), warp 32x64.
// A hi+lo in regs; B 3-stage cp.async ring; np-outer fold keeps accums at 32.
// ============================================================================
__device__ __forceinline__ void fill_b_async(uint32_t dst,
                                             const uint32_t* __restrict__ src,
                                             int tid) {
    const char* s = (const char*)src;
    #pragma unroll
    for (int i = 0; i < 8; i++)
        CP_ASYNC16(dst + i * 4096 + tid * 16, s + i * 4096 + tid * 16);
}

__global__ __launch_bounds__(256, 2) void k_gemm_max(float* __restrict__ out) {
    extern __shared__ char sm[];
    __shared__ int s_last;
    const int tid = threadIdx.x, wid = tid >> 5, lane = tid & 31;
    const int wm = wid >> 1, wn = wid & 1;
    const uint32_t Bring = smem_u32(sm);         // 3 x 32KB

    const int bm = blockIdx.x % MTILES;
    const int bn = blockIdx.x / MTILES;
    const int p0 = bm * MT;
    const uint32_t* imgT = g_imgA + (size_t)bm * TILE_U32;
    const uint32_t* refT = g_refsQ + (size_t)(bn * NTILES) * TILE_U32;

    // prologue: B0 (group0), B1 (group1)
    fill_b_async(Bring, refT, tid);
    CP_COMMIT();
    fill_b_async(Bring + BSTAGE_BYTES, refT + TILE_U32, tid);
    CP_COMMIT();

    // A hi+lo fragments -> registers (live whole kernel)
    uint32_t ahi[2][4][4], alo[2][4][4];
    #pragma unroll
    for (int mf = 0; mf < 2; mf++)
        #pragma unroll
        for (int ks = 0; ks < 4; ks++) {
            const size_t fi = (size_t)(((wm * 2 + mf) * 4 + ks) * 32 + lane) * 4;
            const uint4 wh = *(const uint4*)(imgT + fi);
            const uint4 wl = *(const uint4*)(imgT + 4096 + fi);
            ahi[mf][ks][0] = wh.x; ahi[mf][ks][1] = wh.y;
            ahi[mf][ks][2] = wh.z; ahi[mf][ks][3] = wh.w;
            alo[mf][ks][0] = wl.x; alo[mf][ks][1] = wl.y;
            alo[mf][ks][2] = wl.z; alo[mf][ks][3] = wl.w;
        }

    const uint32_t bOffW = (uint32_t)((wn * 4) * 4 * 32 + lane) * 16;

    int rmax0[2], rmax1[2];
    #pragma unroll
    for (int mf = 0; mf < 2; mf++) { rmax0[mf] = (int)0x80000000; rmax1[mf] = (int)0x80000000; }

    for (int t = 0; t < NTILES; t++) {
        CP_WAIT(1);                      // stage t resident
        __syncthreads();

        if (t + 2 < NTILES) {
            fill_b_async(Bring + (uint32_t)((t + 2) % 3) * BSTAGE_BYTES,
                         refT + (size_t)(t + 2) * TILE_U32, tid);
            CP_COMMIT();
        }

        const uint32_t Bhi = Bring + (uint32_t)(t % 3) * BSTAGE_BYTES + bOffW;
        const uint32_t Blo = Bhi + 16384;

        #pragma unroll
        for (int np = 0; np < 4; np++) {
            int hh[2][2][4], xx[2][2][4];
            #pragma unroll
            for (int mf = 0; mf < 2; mf++)
                #pragma unroll
                for (int h = 0; h < 2; h++)
                    #pragma unroll
                    for (int e = 0; e < 4; e++) { hh[mf][h][e] = 0; xx[mf][h][e] = 0; }

            #pragma unroll
            for (int ks = 0; ks < 4; ks++) {
                const uint32_t fo = (uint32_t)((np * 4 + ks) * 32) * 16;
                uint32_t bh[4], bl[4];
                LDS128(bh[0], bh[1], bh[2], bh[3], Bhi + fo);
                LDS128(bl[0], bl[1], bl[2], bl[3], Blo + fo);
                #pragma unroll
                for (int half = 0; half < 2; half++) {
                    const uint32_t* bhp = bh + 2 * half;
                    const uint32_t* blp = bl + 2 * half;
                    #pragma unroll
                    for (int mf = 0; mf < 2; mf++) {
                        mma_s8(hh[mf][half], ahi[mf][ks], bhp);
                        mma_s8(xx[mf][half], ahi[mf][ks], blp);
                        mma_s8(xx[mf][half], alo[mf][ks], bhp);
                    }
                }
            }

            // fold this np-group (overlaps next group's tensor work)
            #pragma unroll
            for (int mf = 0; mf < 2; mf++)
                #pragma unroll
                for (int h = 0; h < 2; h++) {
                    int s0 = hh[mf][h][0] * 128 + xx[mf][h][0];
                    int s1 = hh[mf][h][1] * 128 + xx[mf][h][1];
                    int s2 = hh[mf][h][2] * 128 + xx[mf][h][2];
                    int s3 = hh[mf][h][3] * 128 + xx[mf][h][3];
                    rmax0[mf] = max(rmax0[mf], max(s0, s1));
                    rmax1[mf] = max(rmax1[mf], max(s2, s3));
                }
        }
    }

    // per-CTA epilogue: reduce 4 lanes sharing a row, one atomic per row
    #pragma unroll
    for (int mf = 0; mf < 2; mf++) {
        int m0 = rmax0[mf], m1 = rmax1[mf];
        m0 = max(m0, __shfl_xor_sync(0xffffffffu, m0, 1));
        m0 = max(m0, __shfl_xor_sync(0xffffffffu, m0, 2));
        m1 = max(m1, __shfl_xor_sync(0xffffffffu, m1, 1));
        m1 = max(m1, __shfl_xor_sync(0xffffffffu, m1, 2));
        if ((lane & 3) == 0) {
            int row = p0 + wm * 32 + mf * 16 + (lane >> 2);
            atomicMax(&g_pmax[row], m0);
            atomicMax(&g_pmax[row + 8], m1);
        }
    }

    // last-block final decode (replaces the k_final launch)
    __threadfence();
    if (tid == 0) s_last = (atomicAdd(&g_done, 1) == NBLK - 1);
    __syncthreads();
    if (s_last) {
        #pragma unroll
        for (int i = 0; i < HW / 256; i++) {
            int p = i * 256 + tid;
            // atomicMax with INT_MIN = coherent atomic read of the final max
            int s = atomicMax(&g_pmax[p], (int)0x80000000);
            out[p] = (float)s * (1.0f / 2097152.0f);
        }
    }
}

// ============================================================================
extern "C" void kernel_launch(void* const* d_in, const int* in_sizes, int n_in,
                              void* d_out, int out_size) {
    const float* refs = (const float*)d_in[0];
    const float* img  = (const float*)d_in[1];
    float* out = (float*)d_out;

    cudaFuncSetAttribute(k_gemm_max, cudaFuncAttributeMaxDynamicSharedMemorySize,
                         DSMEM_GEMM);

    k_prep<<<MTILES + NREF * NTILES, 128, PREP_SMEM>>>(refs, img);
    k_gemm_max<<<NBLK, 256, DSMEM_GEMM>>>(out);
}

// round 9
// speedup vs baseline: 2.4193x; 1.0031x over previous
#include <cuda_runtime.h>
#include <cstdint>

// ============================================================================
// PuzzleSim: out[p] = max over (n,q) of <img_n[:,p], refs_n[n,:,q]>
// R9 = R8 (int8 IMMA 3-pass, 2 CTAs/SM, A in regs, 3-stage B ring, fused
// prep + fused final decode) with accumulator zeroing eliminated: the first
// k-step of every np-group uses mma with a constant-zero C operand
// (D = A*B + 0), removing ~128 MOVs/warp/iter of issue pressure.
// S = 128*Sum(hi*hi) + Sum(hi*lo + lo*hi); sim ~ S/2^21; integer row-max.
// ============================================================================

#define NREF    32
#define CCH     128
#define HW      2304            // 48*48
#define MT      128
#define NT      128
#define NTILES  (HW / NT)       // 18
#define MTILES  (HW / MT)       // 18
#define NBLK    (MTILES * NREF) // 576
#define TILE_U32 8192           // one (hi+lo) frag-linear tile = 32KB
#define BSTAGE_BYTES 32768
#define DSMEM_GEMM (3 * BSTAGE_BYTES)   // 96KB -> 2 CTAs/SM
#define PREP_SMEM  (2 * 128 * 132)      // 33792B

// ---- device scratch ----
// per-tile layout (u32): [pass(2)][blk(8)][ks(4)][lane(32)][reg(4)]
//   A: blk = m16 index (8 x 16 rows);  B: blk = nf-pair (8 x 16 cols)
__device__ uint32_t g_imgA[(size_t)MTILES * TILE_U32];
__device__ uint32_t g_refsQ[(size_t)NBLK * TILE_U32];
__device__ int g_pmax[HW];
__device__ int g_done;

// ============================================================================
// helpers
// ============================================================================
__device__ __forceinline__ uint32_t smem_u32(const void* p) {
    uint32_t a;
    asm("{ .reg .u64 t; cvta.to.shared.u64 t, %1; cvt.u32.u64 %0, t; }"
        : "=r"(a) : "l"(p));
    return a;
}
// accumulate: D = A*B + D
__device__ __forceinline__ void mma_s8(int* c, const uint32_t* a,
                                       const uint32_t* b) {
    asm volatile(
        "mma.sync.aligned.m16n8k32.row.col.s32.s8.s8.s32 "
        "{%0,%1,%2,%3}, {%4,%5,%6,%7}, {%8,%9}, {%0,%1,%2,%3};"
        : "+r"(c[0]), "+r"(c[1]), "+r"(c[2]), "+r"(c[3])
        : "r"(a[0]), "r"(a[1]), "r"(a[2]), "r"(a[3]), "r"(b[0]), "r"(b[1]));
}
// initialize: D = A*B + 0  (no accumulator zero-mov needed)
__device__ __forceinline__ void mma_s8_zc(int* d, const uint32_t* a,
                                          const uint32_t* b) {
    asm volatile(
        "mma.sync.aligned.m16n8k32.row.col.s32.s8.s8.s32 "
        "{%0,%1,%2,%3}, {%4,%5,%6,%7}, {%8,%9}, {%10,%10,%10,%10};"
        : "=r"(d[0]), "=r"(d[1]), "=r"(d[2]), "=r"(d[3])
        : "r"(a[0]), "r"(a[1]), "r"(a[2]), "r"(a[3]), "r"(b[0]), "r"(b[1]),
          "r"(0));
}
#define CP_ASYNC16(dst, src) \
    asm volatile("cp.async.cg.shared.global [%0], [%1], 16;" \
                 :: "r"(dst), "l"(src) : "memory")
#define CP_COMMIT()  asm volatile("cp.async.commit_group;" ::: "memory")
#define CP_WAIT(n)   asm volatile("cp.async.wait_group %0;" :: "n"(n) : "memory")
#define LDS128(r0, r1, r2, r3, addr) \
    asm volatile("ld.shared.v4.b32 {%0,%1,%2,%3}, [%4];" \
                 : "=r"(r0), "=r"(r1), "=r"(r2), "=r"(r3) : "r"(addr))

// quantize a normalized value: q = round(v*2^14), hi=(q+64)>>7, lo=q-128*hi
__device__ __forceinline__ void quant14(float v, char& hi, char& lo) {
    int q = __float2int_rn(v * 16384.f);
    q = max(min(q, 16319), -16319);
    int h = (q + 64) >> 7;
    hi = (char)h;
    lo = (char)(q - (h << 7));
}

// ============================================================================
// K1: fused prep. 594 blocks x 128 thr.
//   blocks [0,18):    img -> A-fragment-linear (+ g_pmax / g_done init)
//   blocks [18,594):  refs -> B-fragment-linear (bid-18 = bn*18 + t)
// ============================================================================
__global__ __launch_bounds__(128) void k_prep(const float* __restrict__ refs,
                                              const float* __restrict__ img) {
    extern __shared__ char sc[];
    char* sh = sc;
    char* sl = sc + 128 * 132;
    const int tid = threadIdx.x;
    const int bid = blockIdx.x;
    const bool is_img = bid < MTILES;

    const float* base;
    if (is_img) {
        const int p = bid * 128 + tid;
        g_pmax[p] = (int)0x80000000;
        if (p == 0) g_done = 0;
        base = img + p;
    } else {
        const int rb = bid - MTILES;
        const int bn = rb / NTILES;
        const int q = (rb % NTILES) * 128 + tid;
        base = refs + (size_t)bn * CCH * HW + q;
    }

    float v[CCH];
    float ss = 0.f;
    #pragma unroll 8
    for (int c = 0; c < CCH; c++) {
        v[c] = base[(size_t)c * HW];
        ss += v[c] * v[c];
    }
    float scale = 1.0f / fmaxf(sqrtf(ss), 1e-12f);
    #pragma unroll 8
    for (int c = 0; c < CCH; c++) {
        char h, l;
        quant14(v[c] * scale, h, l);
        sh[tid * 132 + c] = h;
        sl[tid * 132 + c] = l;
    }
    __syncthreads();

    if (is_img) {
        // A frag mapping: reg0:(r,k) reg1:(r+8,k) reg2:(r,k+16) reg3:(r+8,k+16)
        uint32_t* dst = g_imgA + (size_t)bid * TILE_U32;
        #pragma unroll 4
        for (int w = 0; w < 64; w++) {
            int idx = w * 128 + tid;
            int reg = idx & 3, lane = (idx >> 2) & 31, ks = (idx >> 7) & 3;
            int m16 = (idx >> 9) & 7, pass = idx >> 12;
            int row = 16 * m16 + (lane >> 2) + 8 * (reg & 1);
            int k = 32 * ks + 4 * (lane & 3) + 16 * (reg >> 1);
            const char* s = pass ? sl : sh;
            dst[idx] = *(const uint32_t*)(s + row * 132 + k);
        }
    } else {
        // B frag mapping: r0:(c0,k) r1:(c0,k+16) r2:(c0+8,k) r3:(c0+8,k+16)
        uint32_t* dst = g_refsQ + (size_t)(bid - MTILES) * TILE_U32;
        #pragma unroll 4
        for (int w = 0; w < 64; w++) {
            int idx = w * 128 + tid;
            int reg = idx & 3, lane = (idx >> 2) & 31, ks = (idx >> 7) & 3;
            int nfp = (idx >> 9) & 7, pass = idx >> 12;
            int col = 16 * nfp + (lane >> 2) + 8 * (reg >> 1);
            int k = 32 * ks + 4 * (lane & 3) + 16 * (reg & 1);
            const char* s = pass ? sl : sh;
            dst[idx] = *(const uint32_t*)(s + col * 132 + k);
        }
    }
}

// ============================================================================
// K2: main GEMM+max (+ fused final decode in the last CTA).
// CTA=(bm,bn), 2 CTAs/SM. 8 warps 4(M)x2(N), warp 32x64.
// A hi+lo in regs; B 3-stage cp.async ring; np-outer fold keeps accums at 32.
// ============================================================================
__device__ __forceinline__ void fill_b_async(uint32_t dst,
                                             const uint32_t* __restrict__ src,
                                             int tid) {
    const char* s = (const char*)src;
    #pragma unroll
    for (int i = 0; i < 8; i++)
        CP_ASYNC16(dst + i * 4096 + tid * 16, s + i * 4096 + tid * 16);
}

__global__ __launch_bounds__(256, 2) void k_gemm_max(float* __restrict__ out) {
    extern __shared__ char sm[];
    __shared__ int s_last;
    const int tid = threadIdx.x, wid = tid >> 5, lane = tid & 31;
    const int wm = wid >> 1, wn = wid & 1;
    const uint32_t Bring = smem_u32(sm);         // 3 x 32KB

    const int bm = blockIdx.x % MTILES;
    const int bn = blockIdx.x / MTILES;
    const int p0 = bm * MT;
    const uint32_t* imgT = g_imgA + (size_t)bm * TILE_U32;
    const uint32_t* refT = g_refsQ + (size_t)(bn * NTILES) * TILE_U32;

    // prologue: B0 (group0), B1 (group1)
    fill_b_async(Bring, refT, tid);
    CP_COMMIT();
    fill_b_async(Bring + BSTAGE_BYTES, refT + TILE_U32, tid);
    CP_COMMIT();

    // A hi+lo fragments -> registers (live whole kernel)
    uint32_t ahi[2][4][4], alo[2][4][4];
    #pragma unroll
    for (int mf = 0; mf < 2; mf++)
        #pragma unroll
        for (int ks = 0; ks < 4; ks++) {
            const size_t fi = (size_t)(((wm * 2 + mf) * 4 + ks) * 32 + lane) * 4;
            const uint4 wh = *(const uint4*)(imgT + fi);
            const uint4 wl = *(const uint4*)(imgT + 4096 + fi);
            ahi[mf][ks][0] = wh.x; ahi[mf][ks][1] = wh.y;
            ahi[mf][ks][2] = wh.z; ahi[mf][ks][3] = wh.w;
            alo[mf][ks][0] = wl.x; alo[mf][ks][1] = wl.y;
            alo[mf][ks][2] = wl.z; alo[mf][ks][3] = wl.w;
        }

    const uint32_t bOffW = (uint32_t)((wn * 4) * 4 * 32 + lane) * 16;

    int rmax0[2], rmax1[2];
    #pragma unroll
    for (int mf = 0; mf < 2; mf++) { rmax0[mf] = (int)0x80000000; rmax1[mf] = (int)0x80000000; }

    for (int t = 0; t < NTILES; t++) {
        CP_WAIT(1);                      // stage t resident
        __syncthreads();

        if (t + 2 < NTILES) {
            fill_b_async(Bring + (uint32_t)((t + 2) % 3) * BSTAGE_BYTES,
                         refT + (size_t)(t + 2) * TILE_U32, tid);
            CP_COMMIT();
        }

        const uint32_t Bhi = Bring + (uint32_t)(t % 3) * BSTAGE_BYTES + bOffW;
        const uint32_t Blo = Bhi + 16384;

        #pragma unroll
        for (int np = 0; np < 4; np++) {
            int hh[2][2][4], xx[2][2][4];
            #pragma unroll
            for (int ks = 0; ks < 4; ks++) {
                const uint32_t fo = (uint32_t)((np * 4 + ks) * 32) * 16;
                uint32_t bh[4], bl[4];
                LDS128(bh[0], bh[1], bh[2], bh[3], Bhi + fo);
                LDS128(bl[0], bl[1], bl[2], bl[3], Blo + fo);
                #pragma unroll
                for (int half = 0; half < 2; half++) {
                    const uint32_t* bhp = bh + 2 * half;
                    const uint32_t* blp = bl + 2 * half;
                    #pragma unroll
                    for (int mf = 0; mf < 2; mf++) {
                        if (ks == 0) {
                            // first k-step: D = A*B + 0 (no zeroing movs)
                            mma_s8_zc(hh[mf][half], ahi[mf][0], bhp);
                            mma_s8_zc(xx[mf][half], ahi[mf][0], blp);
                            mma_s8(xx[mf][half], alo[mf][0], bhp);
                        } else {
                            mma_s8(hh[mf][half], ahi[mf][ks], bhp);
                            mma_s8(xx[mf][half], ahi[mf][ks], blp);
                            mma_s8(xx[mf][half], alo[mf][ks], bhp);
                        }
                    }
                }
            }

            // fold this np-group (overlaps next group's tensor work)
            #pragma unroll
            for (int mf = 0; mf < 2; mf++)
                #pragma unroll
                for (int h = 0; h < 2; h++) {
                    int s0 = hh[mf][h][0] * 128 + xx[mf][h][0];
                    int s1 = hh[mf][h][1] * 128 + xx[mf][h][1];
                    int s2 = hh[mf][h][2] * 128 + xx[mf][h][2];
                    int s3 = hh[mf][h][3] * 128 + xx[mf][h][3];
                    rmax0[mf] = max(rmax0[mf], max(s0, s1));
                    rmax1[mf] = max(rmax1[mf], max(s2, s3));
                }
        }
    }

    // per-CTA epilogue: reduce 4 lanes sharing a row, one atomic per row
    #pragma unroll
    for (int mf = 0; mf < 2; mf++) {
        int m0 = rmax0[mf], m1 = rmax1[mf];
        m0 = max(m0, __shfl_xor_sync(0xffffffffu, m0, 1));
        m0 = max(m0, __shfl_xor_sync(0xffffffffu, m0, 2));
        m1 = max(m1, __shfl_xor_sync(0xffffffffu, m1, 1));
        m1 = max(m1, __shfl_xor_sync(0xffffffffu, m1, 2));
        if ((lane & 3) == 0) {
            int row = p0 + wm * 32 + mf * 16 + (lane >> 2);
            atomicMax(&g_pmax[row], m0);
            atomicMax(&g_pmax[row + 8], m1);
        }
    }

    // last-block final decode (replaces a separate k_final launch)
    __threadfence();
    if (tid == 0) s_last = (atomicAdd(&g_done, 1) == NBLK - 1);
    __syncthreads();
    if (s_last) {
        #pragma unroll
        for (int i = 0; i < HW / 256; i++) {
            int p = i * 256 + tid;
            // atomicMax with INT_MIN = coherent atomic read of the final max
            int s = atomicMax(&g_pmax[p], (int)0x80000000);
            out[p] = (float)s * (1.0f / 2097152.0f);
        }
    }
}

// ============================================================================
extern "C" void kernel_launch(void* const* d_in, const int* in_sizes, int n_in,
                              void* d_out, int out_size) {
    const float* refs = (const float*)d_in[0];
    const float* img  = (const float*)d_in[1];
    float* out = (float*)d_out;

    cudaFuncSetAttribute(k_gemm_max, cudaFuncAttributeMaxDynamicSharedMemorySize,
                         DSMEM_GEMM);

    k_prep<<<MTILES + NREF * NTILES, 128, PREP_SMEM>>>(refs, img);
    k_gemm_max<<<NBLK, 256, DSMEM_GEMM>>>(out);
}

// round 10
// speedup vs baseline: 2.4558x; 1.0151x over previous
#include <cuda_runtime.h>
#include <cstdint>

// ============================================================================
// PuzzleSim: out[p] = max over (n,q) of <img_n[:,p], refs_n[n,:,q]>
// R10 = R9 GEMM (int8 IMMA 3-pass, 2 CTAs/SM, A in regs, 3-stage B ring,
// fused final decode) + reworked prep: 4 threads per position (512-thr
// blocks, shfl reduce) to quarter the latency chain and lift prep DRAM
// throughput. GEMM kernel unchanged from R9.
// S = 128*Sum(hi*hi) + Sum(hi*lo + lo*hi); sim ~ S/2^21; integer row-max.
// ============================================================================

#define NREF    32
#define CCH     128
#define HW      2304            // 48*48
#define MT      128
#define NT      128
#define NTILES  (HW / NT)       // 18
#define MTILES  (HW / MT)       // 18
#define NBLK    (MTILES * NREF) // 576
#define TILE_U32 8192           // one (hi+lo) frag-linear tile = 32KB
#define BSTAGE_BYTES 32768
#define DSMEM_GEMM (3 * BSTAGE_BYTES)   // 96KB -> 2 CTAs/SM
#define PREP_SMEM  (2 * 128 * 132)      // 33792B

// ---- device scratch ----
// per-tile layout (u32): [pass(2)][blk(8)][ks(4)][lane(32)][reg(4)]
//   A: blk = m16 index (8 x 16 rows);  B: blk = nf-pair (8 x 16 cols)
__device__ uint32_t g_imgA[(size_t)MTILES * TILE_U32];
__device__ uint32_t g_refsQ[(size_t)NBLK * TILE_U32];
__device__ int g_pmax[HW];
__device__ int g_done;

// ============================================================================
// helpers
// ============================================================================
__device__ __forceinline__ uint32_t smem_u32(const void* p) {
    uint32_t a;
    asm("{ .reg .u64 t; cvta.to.shared.u64 t, %1; cvt.u32.u64 %0, t; }"
        : "=r"(a) : "l"(p));
    return a;
}
// accumulate: D = A*B + D
__device__ __forceinline__ void mma_s8(int* c, const uint32_t* a,
                                       const uint32_t* b) {
    asm volatile(
        "mma.sync.aligned.m16n8k32.row.col.s32.s8.s8.s32 "
        "{%0,%1,%2,%3}, {%4,%5,%6,%7}, {%8,%9}, {%0,%1,%2,%3};"
        : "+r"(c[0]), "+r"(c[1]), "+r"(c[2]), "+r"(c[3])
        : "r"(a[0]), "r"(a[1]), "r"(a[2]), "r"(a[3]), "r"(b[0]), "r"(b[1]));
}
// initialize: D = A*B + 0
__device__ __forceinline__ void mma_s8_zc(int* d, const uint32_t* a,
                                          const uint32_t* b) {
    asm volatile(
        "mma.sync.aligned.m16n8k32.row.col.s32.s8.s8.s32 "
        "{%0,%1,%2,%3}, {%4,%5,%6,%7}, {%8,%9}, {%10,%10,%10,%10};"
        : "=r"(d[0]), "=r"(d[1]), "=r"(d[2]), "=r"(d[3])
        : "r"(a[0]), "r"(a[1]), "r"(a[2]), "r"(a[3]), "r"(b[0]), "r"(b[1]),
          "r"(0));
}
#define CP_ASYNC16(dst, src) \
    asm volatile("cp.async.cg.shared.global [%0], [%1], 16;" \
                 :: "r"(dst), "l"(src) : "memory")
#define CP_COMMIT()  asm volatile("cp.async.commit_group;" ::: "memory")
#define CP_WAIT(n)   asm volatile("cp.async.wait_group %0;" :: "n"(n) : "memory")
#define LDS128(r0, r1, r2, r3, addr) \
    asm volatile("ld.shared.v4.b32 {%0,%1,%2,%3}, [%4];" \
                 : "=r"(r0), "=r"(r1), "=r"(r2), "=r"(r3) : "r"(addr))

// quantize a normalized value: q = round(v*2^14), hi=(q+64)>>7, lo=q-128*hi
__device__ __forceinline__ void quant14(float v, char& hi, char& lo) {
    int q = __float2int_rn(v * 16384.f);
    q = max(min(q, 16319), -16319);
    int h = (q + 64) >> 7;
    hi = (char)h;
    lo = (char)(q - (h << 7));
}

// ============================================================================
// K1: fused prep. 594 blocks x 512 thr; 4 threads per position (quarter =
// tid&3 handles 32 channels), shfl-reduce for the norm.
//   blocks [0,18):    img -> A-fragment-linear (+ g_pmax / g_done init)
//   blocks [18,594):  refs -> B-fragment-linear (bid-18 = bn*18 + t)
// ============================================================================
__global__ __launch_bounds__(512) void k_prep(const float* __restrict__ refs,
                                              const float* __restrict__ img) {
    extern __shared__ char sc[];
    char* sh = sc;
    char* sl = sc + 128 * 132;
    const int tid = threadIdx.x;
    const int bid = blockIdx.x;
    const int pos = tid >> 2;            // 0..127 position within block
    const int quarter = tid & 3;         // channel quarter
    const bool is_img = bid < MTILES;

    const float* base;
    if (is_img) {
        const int p = bid * 128 + pos;
        if (quarter == 0) {
            g_pmax[p] = (int)0x80000000;
            if (p == 0) g_done = 0;
        }
        base = img + p;
    } else {
        const int rb = bid - MTILES;
        const int bn = rb / NTILES;
        const int q = (rb % NTILES) * 128 + pos;
        base = refs + (size_t)bn * CCH * HW + q;
    }
    const float* cb = base + (size_t)(quarter * 32) * HW;

    float v[32];
    float ss = 0.f;
    #pragma unroll 8
    for (int c = 0; c < 32; c++) {
        v[c] = cb[(size_t)c * HW];
        ss += v[c] * v[c];
    }
    // reduce across the 4 threads of this position (lane-aligned quad)
    ss += __shfl_xor_sync(0xffffffffu, ss, 1);
    ss += __shfl_xor_sync(0xffffffffu, ss, 2);
    float scale = 1.0f / fmaxf(sqrtf(ss), 1e-12f);

    #pragma unroll 8
    for (int c = 0; c < 32; c++) {
        char h, l;
        quant14(v[c] * scale, h, l);
        sh[pos * 132 + quarter * 32 + c] = h;
        sl[pos * 132 + quarter * 32 + c] = l;
    }
    __syncthreads();

    if (is_img) {
        // A frag mapping: reg0:(r,k) reg1:(r+8,k) reg2:(r,k+16) reg3:(r+8,k+16)
        uint32_t* dst = g_imgA + (size_t)bid * TILE_U32;
        #pragma unroll 4
        for (int w = 0; w < 16; w++) {
            int idx = w * 512 + tid;
            int reg = idx & 3, lane = (idx >> 2) & 31, ks = (idx >> 7) & 3;
            int m16 = (idx >> 9) & 7, pass = idx >> 12;
            int row = 16 * m16 + (lane >> 2) + 8 * (reg & 1);
            int k = 32 * ks + 4 * (lane & 3) + 16 * (reg >> 1);
            const char* s = pass ? sl : sh;
            dst[idx] = *(const uint32_t*)(s + row * 132 + k);
        }
    } else {
        // B frag mapping: r0:(c0,k) r1:(c0,k+16) r2:(c0+8,k) r3:(c0+8,k+16)
        uint32_t* dst = g_refsQ + (size_t)(bid - MTILES) * TILE_U32;
        #pragma unroll 4
        for (int w = 0; w < 16; w++) {
            int idx = w * 512 + tid;
            int reg = idx & 3, lane = (idx >> 2) & 31, ks = (idx >> 7) & 3;
            int nfp = (idx >> 9) & 7, pass = idx >> 12;
            int col = 16 * nfp + (lane >> 2) + 8 * (reg >> 1);
            int k = 32 * ks + 4 * (lane & 3) + 16 * (reg & 1);
            const char* s = pass ? sl : sh;
            dst[idx] = *(const uint32_t*)(s + col * 132 + k);
        }
    }
}

// ============================================================================
// K2: main GEMM+max (+ fused final decode). Unchanged from R9.
// CTA=(bm,bn), 2 CTAs/SM. 8 warps 4(M)x2(N), warp 32x64.
// ============================================================================
__device__ __forceinline__ void fill_b_async(uint32_t dst,
                                             const uint32_t* __restrict__ src,
                                             int tid) {
    const char* s = (const char*)src;
    #pragma unroll
    for (int i = 0; i < 8; i++)
        CP_ASYNC16(dst + i * 4096 + tid * 16, s + i * 4096 + tid * 16);
}

__global__ __launch_bounds__(256, 2) void k_gemm_max(float* __restrict__ out) {
    extern __shared__ char sm[];
    __shared__ int s_last;
    const int tid = threadIdx.x, wid = tid >> 5, lane = tid & 31;
    const int wm = wid >> 1, wn = wid & 1;
    const uint32_t Bring = smem_u32(sm);         // 3 x 32KB

    const int bm = blockIdx.x % MTILES;
    const int bn = blockIdx.x / MTILES;
    const int p0 = bm * MT;
    const uint32_t* imgT = g_imgA + (size_t)bm * TILE_U32;
    const uint32_t* refT = g_refsQ + (size_t)(bn * NTILES) * TILE_U32;

    fill_b_async(Bring, refT, tid);
    CP_COMMIT();
    fill_b_async(Bring + BSTAGE_BYTES, refT + TILE_U32, tid);
    CP_COMMIT();

    uint32_t ahi[2][4][4], alo[2][4][4];
    #pragma unroll
    for (int mf = 0; mf < 2; mf++)
        #pragma unroll
        for (int ks = 0; ks < 4; ks++) {
            const size_t fi = (size_t)(((wm * 2 + mf) * 4 + ks) * 32 + lane) * 4;
            const uint4 wh = *(const uint4*)(imgT + fi);
            const uint4 wl = *(const uint4*)(imgT + 4096 + fi);
            ahi[mf][ks][0] = wh.x; ahi[mf][ks][1] = wh.y;
            ahi[mf][ks][2] = wh.z; ahi[mf][ks][3] = wh.w;
            alo[mf][ks][0] = wl.x; alo[mf][ks][1] = wl.y;
            alo[mf][ks][2] = wl.z; alo[mf][ks][3] = wl.w;
        }

    const uint32_t bOffW = (uint32_t)((wn * 4) * 4 * 32 + lane) * 16;

    int rmax0[2], rmax1[2];
    #pragma unroll
    for (int mf = 0; mf < 2; mf++) { rmax0[mf] = (int)0x80000000; rmax1[mf] = (int)0x80000000; }

    for (int t = 0; t < NTILES; t++) {
        CP_WAIT(1);
        __syncthreads();

        if (t + 2 < NTILES) {
            fill_b_async(Bring + (uint32_t)((t + 2) % 3) * BSTAGE_BYTES,
                         refT + (size_t)(t + 2) * TILE_U32, tid);
            CP_COMMIT();
        }

        const uint32_t Bhi = Bring + (uint32_t)(t % 3) * BSTAGE_BYTES + bOffW;
        const uint32_t Blo = Bhi + 16384;

        #pragma unroll
        for (int np = 0; np < 4; np++) {
            int hh[2][2][4], xx[2][2][4];
            #pragma unroll
            for (int ks = 0; ks < 4; ks++) {
                const uint32_t fo = (uint32_t)((np * 4 + ks) * 32) * 16;
                uint32_t bh[4], bl[4];
                LDS128(bh[0], bh[1], bh[2], bh[3], Bhi + fo);
                LDS128(bl[0], bl[1], bl[2], bl[3], Blo + fo);
                #pragma unroll
                for (int half = 0; half < 2; half++) {
                    const uint32_t* bhp = bh + 2 * half;
                    const uint32_t* blp = bl + 2 * half;
                    #pragma unroll
                    for (int mf = 0; mf < 2; mf++) {
                        if (ks == 0) {
                            mma_s8_zc(hh[mf][half], ahi[mf][0], bhp);
                            mma_s8_zc(xx[mf][half], ahi[mf][0], blp);
                            mma_s8(xx[mf][half], alo[mf][0], bhp);
                        } else {
                            mma_s8(hh[mf][half], ahi[mf][ks], bhp);
                            mma_s8(xx[mf][half], ahi[mf][ks], blp);
                            mma_s8(xx[mf][half], alo[mf][ks], bhp);
                        }
                    }
                }
            }

            #pragma unroll
            for (int mf = 0; mf < 2; mf++)
                #pragma unroll
                for (int h = 0; h < 2; h++) {
                    int s0 = hh[mf][h][0] * 128 + xx[mf][h][0];
                    int s1 = hh[mf][h][1] * 128 + xx[mf][h][1];
                    int s2 = hh[mf][h][2] * 128 + xx[mf][h][2];
                    int s3 = hh[mf][h][3] * 128 + xx[mf][h][3];
                    rmax0[mf] = max(rmax0[mf], max(s0, s1));
                    rmax1[mf] = max(rmax1[mf], max(s2, s3));
                }
        }
    }

    #pragma unroll
    for (int mf = 0; mf < 2; mf++) {
        int m0 = rmax0[mf], m1 = rmax1[mf];
        m0 = max(m0, __shfl_xor_sync(0xffffffffu, m0, 1));
        m0 = max(m0, __shfl_xor_sync(0xffffffffu, m0, 2));
        m1 = max(m1, __shfl_xor_sync(0xffffffffu, m1, 1));
        m1 = max(m1, __shfl_xor_sync(0xffffffffu, m1, 2));
        if ((lane & 3) == 0) {
            int row = p0 + wm * 32 + mf * 16 + (lane >> 2);
            atomicMax(&g_pmax[row], m0);
            atomicMax(&g_pmax[row + 8], m1);
        }
    }

    // last-block final decode
    __threadfence();
    if (tid == 0) s_last = (atomicAdd(&g_done, 1) == NBLK - 1);
    __syncthreads();
    if (s_last) {
        #pragma unroll
        for (int i = 0; i < HW / 256; i++) {
            int p = i * 256 + tid;
            int s = atomicMax(&g_pmax[p], (int)0x80000000);
            out[p] = (float)s * (1.0f / 2097152.0f);
        }
    }
}

// ============================================================================
extern "C" void kernel_launch(void* const* d_in, const int* in_sizes, int n_in,
                              void* d_out, int out_size) {
    const float* refs = (const float*)d_in[0];
    const float* img  = (const float*)d_in[1];
    float* out = (float*)d_out;

    cudaFuncSetAttribute(k_gemm_max, cudaFuncAttributeMaxDynamicSharedMemorySize,
                         DSMEM_GEMM);

    k_prep<<<MTILES + NREF * NTILES, 512, PREP_SMEM>>>(refs, img);
    k_gemm_max<<<NBLK, 256, DSMEM_GEMM>>>(out);
}